// round 8
// baseline (speedup 1.0000x reference)
#include <cuda_runtime.h>
#include <cuda_fp16.h>
#include <math.h>
#include <stdint.h>

#define D   768
#define H   12
#define HD  64
#define B1  2048
#define B2  8192

// Scratch (allocation-free rule: __device__ globals)
__device__ float g_Q[B1 * D];
__device__ float g_K[B2 * D];
__device__ float g_V[B2 * D];
__device__ float g_O[B1 * D];
__device__ __half g_Qh16[B1 * D];
__device__ __half g_Ql16[B1 * D];
__device__ __half g_Kh16[B2 * D];
__device__ __half g_Vh16[B2 * D];

__device__ __forceinline__ float decode_scalar(const void* p) {
    int iv = *(const int*)p;
    if (iv >= -1000000 && iv <= 1000000) return (float)iv;
    return *(const float*)p;
}

// ---- fp16 split helpers ----------------------------------------------------
__device__ __forceinline__ void split2h(float x0, float x1,
                                        uint32_t& hi, uint32_t& lo) {
    __half2 h = __floats2half2_rn(x0, x1);
    float r0 = x0 - __low2float(h);
    float r1 = x1 - __high2float(h);
    __half2 l = __floats2half2_rn(r0, r1);
    hi = *reinterpret_cast<uint32_t*>(&h);
    lo = *reinterpret_cast<uint32_t*>(&l);
}

__device__ __forceinline__ uint32_t pack2h(float x0, float x1) {
    __half2 h = __floats2half2_rn(x0, x1);
    return *reinterpret_cast<uint32_t*>(&h);
}

__device__ __forceinline__ void split4h(float4 v, uint2& hi, uint2& lo) {
    split2h(v.x, v.y, hi.x, lo.x);
    split2h(v.z, v.w, hi.y, lo.y);
}

// ---- mma + ldmatrix --------------------------------------------------------
__device__ __forceinline__ void mma_f16(float c[4], const uint32_t a[4],
                                        const uint32_t b[2]) {
    asm volatile(
        "mma.sync.aligned.m16n8k16.row.col.f32.f16.f16.f32 "
        "{%0,%1,%2,%3}, {%4,%5,%6,%7}, {%8,%9}, {%0,%1,%2,%3};"
        : "+f"(c[0]), "+f"(c[1]), "+f"(c[2]), "+f"(c[3])
        : "r"(a[0]), "r"(a[1]), "r"(a[2]), "r"(a[3]), "r"(b[0]), "r"(b[1]));
}

__device__ __forceinline__ uint32_t smem_u32(const void* p) {
    uint32_t a;
    asm("{ .reg .u64 t; cvta.to.shared.u64 t, %1; cvt.u32.u64 %0, t; }"
        : "=r"(a) : "l"(p));
    return a;
}

__device__ __forceinline__ void ldsm_x4(uint32_t r[4], uint32_t addr) {
    asm volatile("ldmatrix.sync.aligned.m8n8.x4.shared.b16 {%0,%1,%2,%3}, [%4];"
                 : "=r"(r[0]), "=r"(r[1]), "=r"(r[2]), "=r"(r[3]) : "r"(addr));
}
__device__ __forceinline__ void ldsm_x2(uint32_t r[2], uint32_t addr) {
    asm volatile("ldmatrix.sync.aligned.m8n8.x2.shared.b16 {%0,%1}, [%2];"
                 : "=r"(r[0]), "=r"(r[1]) : "r"(addr));
}
__device__ __forceinline__ void ldsm_x2t(uint32_t r[2], uint32_t addr) {
    asm volatile("ldmatrix.sync.aligned.m8n8.x2.trans.shared.b16 {%0,%1}, [%2];"
                 : "=r"(r[0]), "=r"(r[1]) : "r"(addr));
}

// ---------------------------------------------------------------------------
// C[M,N] = A[M,K] * B[N,K]^T via fp16x3 emulated fp32 mma. (unchanged R7)
// ---------------------------------------------------------------------------
#define WS   20
#define ARR  (128 * WS)
#define STG  (4 * ARR)
__global__ __launch_bounds__(256) void gemm_f16x3_kernel(
    const float* __restrict__ A, const float* __restrict__ B,
    float* __restrict__ C, int M, int N, int K)
{
    extern __shared__ uint32_t S[];
    const uint32_t sb = smem_u32(S);

    const int tid = threadIdx.x;
    const int w = tid >> 5, lane = tid & 31;
    const int g = lane >> 2, t = lane & 3;
    const int mw = w >> 2, nw = w & 3;
    const int m0 = blockIdx.y * 128, n0 = blockIdx.x * 128;

    float acc[4][4][4];
    #pragma unroll
    for (int mi = 0; mi < 4; mi++)
        #pragma unroll
        for (int ni = 0; ni < 4; ni++)
            #pragma unroll
            for (int e = 0; e < 4; e++) acc[mi][ni][e] = 0.f;

    const int aoff = (mw * 64 + (lane & 15)) * WS + (lane >> 4) * 4;
    const int boff = (nw * 32 + (lane & 7)) * WS + ((lane >> 3) & 1) * 4;

    const int NCH = K >> 5;
    for (int ch = 0; ch < NCH; ch++) {
        uint32_t* st = S + (ch & 1) * STG;
        #pragma unroll
        for (int p = 0; p < 4; p++) {
            int idx = tid + p * 256;
            int r = idx >> 3, c4 = idx & 7;
            float4 va = *(const float4*)(A + (size_t)(m0 + r) * K + ch * 32 + c4 * 4);
            uint2 hi, lo; split4h(va, hi, lo);
            *(uint2*)&st[r * WS + c4 * 2] = hi;
            *(uint2*)&st[ARR + r * WS + c4 * 2] = lo;
        }
        #pragma unroll
        for (int p = 0; p < 4; p++) {
            int idx = tid + p * 256;
            int r = idx >> 3, c4 = idx & 7;
            float4 vb = *(const float4*)(B + (size_t)(n0 + r) * K + ch * 32 + c4 * 4);
            uint2 hi, lo; split4h(vb, hi, lo);
            *(uint2*)&st[2 * ARR + r * WS + c4 * 2] = hi;
            *(uint2*)&st[3 * ARR + r * WS + c4 * 2] = lo;
        }
        __syncthreads();

        const uint32_t sbase = sb + (ch & 1) * (STG * 4);
        #pragma unroll
        for (int ks = 0; ks < 2; ks++) {
            int kw = ks * 8;
            uint32_t ah[4][4], al[4][4];
            #pragma unroll
            for (int mi = 0; mi < 4; mi++) {
                uint32_t ra = sbase + (aoff + mi * 16 * WS + kw) * 4;
                ldsm_x4(ah[mi], ra);
                ldsm_x4(al[mi], ra + ARR * 4);
            }
            #pragma unroll
            for (int ni = 0; ni < 4; ni++) {
                uint32_t rb = sbase + (2 * ARR + boff + ni * 8 * WS + kw) * 4;
                uint32_t bh[2], bl[2];
                ldsm_x2(bh, rb);
                ldsm_x2(bl, rb + ARR * 4);
                #pragma unroll
                for (int mi = 0; mi < 4; mi++) {
                    mma_f16(acc[mi][ni], ah[mi], bh);
                    mma_f16(acc[mi][ni], ah[mi], bl);
                    mma_f16(acc[mi][ni], al[mi], bh);
                }
            }
        }
    }

    #pragma unroll
    for (int mi = 0; mi < 4; mi++) {
        int r0 = m0 + mw * 64 + mi * 16 + g;
        #pragma unroll
        for (int ni = 0; ni < 4; ni++) {
            int c = n0 + nw * 32 + ni * 8 + 2 * t;
            *(float2*)&C[(size_t)r0 * N + c]       = make_float2(acc[mi][ni][0], acc[mi][ni][1]);
            *(float2*)&C[(size_t)(r0 + 8) * N + c] = make_float2(acc[mi][ni][2], acc[mi][ni][3]);
        }
    }
}

// ---------------------------------------------------------------------------
// Per-head L2 norm + fp16 conversion: reads fp32 X, writes Hi (and Lo if
// non-null) of the normalized value. 64-wide head chunks.
// ---------------------------------------------------------------------------
__global__ __launch_bounds__(768) void headnorm_cvt_kernel(
    const float* __restrict__ X, __half* __restrict__ Hi,
    __half* __restrict__ Lo)
{
    const int row = blockIdx.x;
    const int t = threadIdx.x;
    float v = X[(size_t)row * D + t];
    float s = v * v;
    #pragma unroll
    for (int o = 16; o; o >>= 1) s += __shfl_xor_sync(0xffffffffu, s, o);
    __shared__ float ws[24];
    if ((t & 31) == 0) ws[t >> 5] = s;
    __syncthreads();
    int head = t >> 6;
    float sum = ws[head * 2] + ws[head * 2 + 1];
    float scale = 1.0f / fmaxf(sqrtf(sum), 1e-12f);
    float nv = v * scale;
    __half hb = __float2half_rn(nv);
    Hi[(size_t)row * D + t] = hb;
    if (Lo) Lo[(size_t)row * D + t] = __float2half_rn(nv - __half2float(hb));
}

// ---------------------------------------------------------------------------
// Elementwise fp32 -> fp16 (V), vectorized over float4 / uint2.
// ---------------------------------------------------------------------------
__global__ __launch_bounds__(256) void vconv_kernel(
    const float* __restrict__ V, __half* __restrict__ Vh)
{
    int i = blockIdx.x * 256 + threadIdx.x;     // over B2*D/4
    float4 v = ((const float4*)V)[i];
    uint2 h;
    h.x = pack2h(v.x, v.y);
    h.y = pack2h(v.z, v.w);
    ((uint2*)Vh)[i] = h;
}

// ---------------------------------------------------------------------------
// Flash attention, fp16 mma, preconverted fp16 inputs (numerics == R7):
//   S = (Qh + Ql) . Kh^T ; P as fp16 of p*2^-14 ; O += P . V^T
// Block: 128 q rows x 1 head, 8 warps in 4x2 grid (warp tile 32x32 of S).
// smem: Qh/Ql/Ph [128][VS], Kh/Vh [64][VS], part[8][32]. 74752 B -> occ 2.
// ---------------------------------------------------------------------------
#define VS 36
#define PSCALE   6.103515625e-05f   // 2^-14
#define PUNSCALE 16384.0f           // 2^14
__global__ __launch_bounds__(256, 2) void attn_kernel(
    const __half* __restrict__ Qh16, const __half* __restrict__ Ql16,
    const __half* __restrict__ Kh16, const __half* __restrict__ Vh16,
    float* __restrict__ O, const void* __restrict__ invt_raw)
{
    extern __shared__ uint32_t sm[];
    uint32_t* Qh = sm;                  // [128 q][VS]
    uint32_t* Ql = Qh + 128 * VS;
    uint32_t* Kh = Ql + 128 * VS;       // [64 key][VS]
    uint32_t* Vh = Kh + 64 * VS;        // [64 key][VS] (natural layout)
    uint32_t* Ph = Vh + 64 * VS;        // [128 q][VS]
    float*    part = (float*)(Ph + 128 * VS);   // [8][32]

    const uint32_t sb = smem_u32(sm);
    const uint32_t QhO = 0, QlO = 128 * VS * 4, KhO = 2 * 128 * VS * 4,
                   VhO = KhO + 64 * VS * 4, PhO = VhO + 64 * VS * 4;

    const int tid = threadIdx.x;
    const int w = tid >> 5, lane = tid & 31;
    const int g = lane >> 2, t = lane & 3;
    const int mw = w >> 1, nw = w & 1;            // 4 x 2 warp grid
    const int h = blockIdx.y;
    const int q0 = blockIdx.x * 128;
    const float invt = decode_scalar(invt_raw);

    // ldmatrix lane-address offsets (words)
    const int abase = (mw * 32 + (lane & 15)) * VS + (lane >> 4) * 4;
    const int boff  = (nw * 32 + (lane & 7)) * VS + ((lane >> 3) & 1) * 4;
    const int voffr = (lane & 7) + ((lane >> 3) & 1) * 8;

    // Load Q tile [128 q][d] hi+lo (preconverted fp16)
    #pragma unroll
    for (int p = 0; p < 8; p++) {
        int idx = tid + p * 256;          // 2048 uint2 per array
        int r = idx >> 4, c4 = idx & 15;
        const size_t go = (size_t)(q0 + r) * D + h * HD + c4 * 4;
        *(uint2*)&Qh[r * VS + c4 * 2] = *(const uint2*)(Qh16 + go);
        *(uint2*)&Ql[r * VS + c4 * 2] = *(const uint2*)(Ql16 + go);
    }

    float l[2][2] = {{0.f, 0.f}, {0.f, 0.f}};
    float o[2][4][4];
    #pragma unroll
    for (int mi = 0; mi < 2; mi++)
        #pragma unroll
        for (int ni = 0; ni < 4; ni++)
            #pragma unroll
            for (int e = 0; e < 4; e++) o[mi][ni][e] = 0.f;

    __syncthreads();

    for (int n0 = 0; n0 < B2; n0 += 64) {
        // K/V tiles [64 key][d], fp16 direct
        #pragma unroll
        for (int p = 0; p < 4; p++) {
            int idx = tid + p * 256;
            int r = idx >> 4, c4 = idx & 15;
            const size_t go = (size_t)(n0 + r) * D + h * HD + c4 * 4;
            *(uint2*)&Kh[r * VS + c4 * 2] = *(const uint2*)(Kh16 + go);
            *(uint2*)&Vh[r * VS + c4 * 2] = *(const uint2*)(Vh16 + go);
        }
        __syncthreads();

        // S = (Qh + Ql) . Kh^T
        float s[2][4][4];
        #pragma unroll
        for (int mi = 0; mi < 2; mi++)
            #pragma unroll
            for (int ni = 0; ni < 4; ni++)
                #pragma unroll
                for (int e = 0; e < 4; e++) s[mi][ni][e] = 0.f;

        #pragma unroll
        for (int ks = 0; ks < 4; ks++) {
            int kw = ks * 8;
            uint32_t ah[2][4], al[2][4];
            #pragma unroll
            for (int mi = 0; mi < 2; mi++) {
                ldsm_x4(ah[mi], sb + QhO + (abase + mi * 16 * VS + kw) * 4);
                ldsm_x4(al[mi], sb + QlO + (abase + mi * 16 * VS + kw) * 4);
            }
            #pragma unroll
            for (int ni = 0; ni < 4; ni++) {
                uint32_t bh[2];
                ldsm_x2(bh, sb + KhO + (boff + ni * 8 * VS + kw) * 4);
                #pragma unroll
                for (int mi = 0; mi < 2; mi++) {
                    mma_f16(s[mi][ni], ah[mi], bh);
                    mma_f16(s[mi][ni], al[mi], bh);
                }
            }
        }

        // exp + fp32 row-sum partials + store scaled-fp16 P
        float rs[2][2] = {{0.f, 0.f}, {0.f, 0.f}};
        #pragma unroll
        for (int mi = 0; mi < 2; mi++) {
            #pragma unroll
            for (int ni = 0; ni < 4; ni++) {
                float p0 = __expf(s[mi][ni][0] * invt);
                float p1 = __expf(s[mi][ni][1] * invt);
                float p2 = __expf(s[mi][ni][2] * invt);
                float p3 = __expf(s[mi][ni][3] * invt);
                rs[mi][0] += p0 + p1; rs[mi][1] += p2 + p3;
                int wp = nw * 16 + ni * 4 + t;
                int rr = mw * 32 + mi * 16 + g;
                Ph[rr * VS + wp]       = pack2h(p0 * PSCALE, p1 * PSCALE);
                Ph[(rr + 8) * VS + wp] = pack2h(p2 * PSCALE, p3 * PSCALE);
            }
        }
        #pragma unroll
        for (int mi = 0; mi < 2; mi++)
            #pragma unroll
            for (int hf = 0; hf < 2; hf++) {
                float r = rs[mi][hf];
                r += __shfl_xor_sync(0xffffffffu, r, 1);
                r += __shfl_xor_sync(0xffffffffu, r, 2);
                rs[mi][hf] = r;
            }
        if (t == 0) {
            part[w * 32 + 0 * 8 + g]      = rs[0][0];
            part[w * 32 + 1 * 8 + g]      = rs[0][1];
            part[w * 32 + 16 + 0 * 8 + g] = rs[1][0];
            part[w * 32 + 16 + 1 * 8 + g] = rs[1][1];
        }
        __syncthreads();

        // O += P . V (V transposed inside ldmatrix)
        #pragma unroll
        for (int ks = 0; ks < 4; ks++) {
            int kw = ks * 8;
            uint32_t ap[2][4];
            #pragma unroll
            for (int mi = 0; mi < 2; mi++)
                ldsm_x4(ap[mi], sb + PhO + (abase + mi * 16 * VS + kw) * 4);
            #pragma unroll
            for (int ni = 0; ni < 4; ni++) {
                uint32_t bv[2];
                uint32_t rv = sb + VhO +
                    ((ks * 16 + voffr) * VS + nw * 16 + ni * 4) * 4;
                ldsm_x2t(bv, rv);
                #pragma unroll
                for (int mi = 0; mi < 2; mi++)
                    mma_f16(o[mi][ni], ap[mi], bv);
            }
        }

        // accumulate row sums from both nw warps sharing these rows
        #pragma unroll
        for (int mi = 0; mi < 2; mi++)
            #pragma unroll
            for (int hf = 0; hf < 2; hf++) {
                int idx = mi * 16 + hf * 8 + g;
                l[mi][hf] += part[(2 * mw) * 32 + idx]
                           + part[(2 * mw + 1) * 32 + idx];
            }
        __syncthreads();
    }

    // epilogue: undo 2^-14 P scaling and normalize
    #pragma unroll
    for (int mi = 0; mi < 2; mi++) {
        float i0 = PUNSCALE / l[mi][0], i1 = PUNSCALE / l[mi][1];
        int gr0 = q0 + mw * 32 + mi * 16 + g;
        #pragma unroll
        for (int ni = 0; ni < 4; ni++) {
            int c = h * HD + nw * 32 + ni * 8 + 2 * t;
            *(float2*)&O[(size_t)gr0 * D + c] =
                make_float2(o[mi][ni][0] * i0, o[mi][ni][1] * i0);
            *(float2*)&O[(size_t)(gr0 + 8) * D + c] =
                make_float2(o[mi][ni][2] * i1, o[mi][ni][3] * i1);
        }
    }
}

// ---------------------------------------------------------------------------
// Full-row L2 norm of X[2048, 768], in place.
// ---------------------------------------------------------------------------
__global__ __launch_bounds__(256) void rownorm_kernel(float* __restrict__ X)
{
    const int row = blockIdx.x;
    const int t = threadIdx.x;
    float* xr = X + (size_t)row * D;
    float s = 0.f;
    for (int i = t; i < D; i += 256) { float v = xr[i]; s += v * v; }
    #pragma unroll
    for (int o = 16; o; o >>= 1) s += __shfl_xor_sync(0xffffffffu, s, o);
    __shared__ float red[8];
    if ((t & 31) == 0) red[t >> 5] = s;
    __syncthreads();
    float tot = 0.f;
    #pragma unroll
    for (int i = 0; i < 8; i++) tot += red[i];
    float scale = 1.0f / fmaxf(sqrtf(tot), 1e-12f);
    for (int i = t; i < D; i += 256) xr[i] *= scale;
}

// ---------------------------------------------------------------------------
extern "C" void kernel_launch(void* const* d_in, const int* in_sizes, int n_in,
                              void* d_out, int out_size)
{
    (void)in_sizes; (void)n_in; (void)out_size;
    const float* x1 = (const float*)d_in[0];
    const float* x2 = (const float*)d_in[1];
    const float* Wq = (const float*)d_in[2];
    const float* Wk = (const float*)d_in[3];
    const float* Wv = (const float*)d_in[4];
    const float* Wo = (const float*)d_in[5];
    const void*  invt = d_in[6];
    float* out = (float*)d_out;

    void *pQ, *pK, *pV, *pO, *pQh, *pQl, *pKh, *pVh;
    cudaGetSymbolAddress(&pQ, g_Q);
    cudaGetSymbolAddress(&pK, g_K);
    cudaGetSymbolAddress(&pV, g_V);
    cudaGetSymbolAddress(&pO, g_O);
    cudaGetSymbolAddress(&pQh, g_Qh16);
    cudaGetSymbolAddress(&pQl, g_Ql16);
    cudaGetSymbolAddress(&pKh, g_Kh16);
    cudaGetSymbolAddress(&pVh, g_Vh16);

    // Projections (fp16x3, double-buffered, ldmatrix)
    const int gsmem = 2 * STG * 4;   // 81920 B
    cudaFuncSetAttribute(gemm_f16x3_kernel,
                         cudaFuncAttributeMaxDynamicSharedMemorySize, gsmem);
    gemm_f16x3_kernel<<<dim3(D/128, B1/128), 256, gsmem>>>(x1, Wq, (float*)pQ, B1, D, D);
    gemm_f16x3_kernel<<<dim3(D/128, B2/128), 256, gsmem>>>(x2, Wk, (float*)pK, B2, D, D);
    gemm_f16x3_kernel<<<dim3(D/128, B2/128), 256, gsmem>>>(x2, Wv, (float*)pV, B2, D, D);

    // Per-head cosine normalization + fp16 conversion
    headnorm_cvt_kernel<<<B1, 768>>>((float*)pQ, (__half*)pQh, (__half*)pQl);
    headnorm_cvt_kernel<<<B2, 768>>>((float*)pK, (__half*)pKh, nullptr);
    vconv_kernel<<<(B2 * D / 4) / 256, 256>>>((float*)pV, (__half*)pVh);

    // Flash attention (128-q tiles, fp16 inputs)
    const int smem_bytes = (512 * VS) * 4 + 8 * 32 * 4;   // 74752 B
    cudaFuncSetAttribute(attn_kernel,
                         cudaFuncAttributeMaxDynamicSharedMemorySize, smem_bytes);
    attn_kernel<<<dim3(B1/128, H), 256, smem_bytes>>>(
        (__half*)pQh, (__half*)pQl, (__half*)pKh, (__half*)pVh, (float*)pO, invt);

    // Output projection into d_out, then in-place row norm
    gemm_f16x3_kernel<<<dim3(D/128, B1/128), 256, gsmem>>>((float*)pO, Wo, out, B1, D, D);
    rownorm_kernel<<<B1, 256>>>(out);
}

// round 12
// speedup vs baseline: 1.0909x; 1.0909x over previous
#include <cuda_runtime.h>
#include <cuda_fp16.h>
#include <math.h>
#include <stdint.h>

#define D   768
#define H   12
#define HD  64
#define B1  2048
#define B2  8192

// Scratch (allocation-free rule: __device__ globals)
__device__ float g_Q[B1 * D];
__device__ float g_K[B2 * D];
__device__ float g_V[B2 * D];
__device__ float g_O[B1 * D];
__device__ __half g_Qh16[B1 * D];
__device__ __half g_Ql16[B1 * D];
__device__ __half g_Kh16[B2 * D];
__device__ __half g_Vh16[B2 * D];

__device__ __forceinline__ float decode_scalar(const void* p) {
    int iv = *(const int*)p;
    if (iv >= -1000000 && iv <= 1000000) return (float)iv;
    return *(const float*)p;
}

// ---- fp16 split helpers ----------------------------------------------------
__device__ __forceinline__ void split2h(float x0, float x1,
                                        uint32_t& hi, uint32_t& lo) {
    __half2 h = __floats2half2_rn(x0, x1);
    float r0 = x0 - __low2float(h);
    float r1 = x1 - __high2float(h);
    __half2 l = __floats2half2_rn(r0, r1);
    hi = *reinterpret_cast<uint32_t*>(&h);
    lo = *reinterpret_cast<uint32_t*>(&l);
}

__device__ __forceinline__ uint32_t pack2h(float x0, float x1) {
    __half2 h = __floats2half2_rn(x0, x1);
    return *reinterpret_cast<uint32_t*>(&h);
}

__device__ __forceinline__ void split4h(float4 v, uint2& hi, uint2& lo) {
    split2h(v.x, v.y, hi.x, lo.x);
    split2h(v.z, v.w, hi.y, lo.y);
}

// ---- mma + ldmatrix + cp.async ----------------------------------------------
__device__ __forceinline__ void mma_f16(float c[4], const uint32_t a[4],
                                        const uint32_t b[2]) {
    asm volatile(
        "mma.sync.aligned.m16n8k16.row.col.f32.f16.f16.f32 "
        "{%0,%1,%2,%3}, {%4,%5,%6,%7}, {%8,%9}, {%0,%1,%2,%3};"
        : "+f"(c[0]), "+f"(c[1]), "+f"(c[2]), "+f"(c[3])
        : "r"(a[0]), "r"(a[1]), "r"(a[2]), "r"(a[3]), "r"(b[0]), "r"(b[1]));
}

__device__ __forceinline__ uint32_t smem_u32(const void* p) {
    uint32_t a;
    asm("{ .reg .u64 t; cvta.to.shared.u64 t, %1; cvt.u32.u64 %0, t; }"
        : "=r"(a) : "l"(p));
    return a;
}

__device__ __forceinline__ void ldsm_x4(uint32_t r[4], uint32_t addr) {
    asm volatile("ldmatrix.sync.aligned.m8n8.x4.shared.b16 {%0,%1,%2,%3}, [%4];"
                 : "=r"(r[0]), "=r"(r[1]), "=r"(r[2]), "=r"(r[3]) : "r"(addr));
}
__device__ __forceinline__ void ldsm_x2(uint32_t r[2], uint32_t addr) {
    asm volatile("ldmatrix.sync.aligned.m8n8.x2.shared.b16 {%0,%1}, [%2];"
                 : "=r"(r[0]), "=r"(r[1]) : "r"(addr));
}
__device__ __forceinline__ void ldsm_x2t(uint32_t r[2], uint32_t addr) {
    asm volatile("ldmatrix.sync.aligned.m8n8.x2.trans.shared.b16 {%0,%1}, [%2];"
                 : "=r"(r[0]), "=r"(r[1]) : "r"(addr));
}
__device__ __forceinline__ void cp16(uint32_t saddr, const void* gaddr) {
    asm volatile("cp.async.cg.shared.global [%0], [%1], 16;"
                 :: "r"(saddr), "l"(gaddr) : "memory");
}

// ---------------------------------------------------------------------------
// C[M,N] = A[M,K] * B[N,K]^T via fp16x3 emulated fp32 mma. (unchanged R7)
// ---------------------------------------------------------------------------
#define WS   20
#define ARR  (128 * WS)
#define STG  (4 * ARR)
__global__ __launch_bounds__(256) void gemm_f16x3_kernel(
    const float* __restrict__ A, const float* __restrict__ B,
    float* __restrict__ C, int M, int N, int K)
{
    extern __shared__ uint32_t S[];
    const uint32_t sb = smem_u32(S);

    const int tid = threadIdx.x;
    const int w = tid >> 5, lane = tid & 31;
    const int g = lane >> 2, t = lane & 3;
    const int mw = w >> 2, nw = w & 3;
    const int m0 = blockIdx.y * 128, n0 = blockIdx.x * 128;

    float acc[4][4][4];
    #pragma unroll
    for (int mi = 0; mi < 4; mi++)
        #pragma unroll
        for (int ni = 0; ni < 4; ni++)
            #pragma unroll
            for (int e = 0; e < 4; e++) acc[mi][ni][e] = 0.f;

    const int aoff = (mw * 64 + (lane & 15)) * WS + (lane >> 4) * 4;
    const int boff = (nw * 32 + (lane & 7)) * WS + ((lane >> 3) & 1) * 4;

    const int NCH = K >> 5;
    for (int ch = 0; ch < NCH; ch++) {
        uint32_t* st = S + (ch & 1) * STG;
        #pragma unroll
        for (int p = 0; p < 4; p++) {
            int idx = tid + p * 256;
            int r = idx >> 3, c4 = idx & 7;
            float4 va = *(const float4*)(A + (size_t)(m0 + r) * K + ch * 32 + c4 * 4);
            uint2 hi, lo; split4h(va, hi, lo);
            *(uint2*)&st[r * WS + c4 * 2] = hi;
            *(uint2*)&st[ARR + r * WS + c4 * 2] = lo;
        }
        #pragma unroll
        for (int p = 0; p < 4; p++) {
            int idx = tid + p * 256;
            int r = idx >> 3, c4 = idx & 7;
            float4 vb = *(const float4*)(B + (size_t)(n0 + r) * K + ch * 32 + c4 * 4);
            uint2 hi, lo; split4h(vb, hi, lo);
            *(uint2*)&st[2 * ARR + r * WS + c4 * 2] = hi;
            *(uint2*)&st[3 * ARR + r * WS + c4 * 2] = lo;
        }
        __syncthreads();

        const uint32_t sbase = sb + (ch & 1) * (STG * 4);
        #pragma unroll
        for (int ks = 0; ks < 2; ks++) {
            int kw = ks * 8;
            uint32_t ah[4][4], al[4][4];
            #pragma unroll
            for (int mi = 0; mi < 4; mi++) {
                uint32_t ra = sbase + (aoff + mi * 16 * WS + kw) * 4;
                ldsm_x4(ah[mi], ra);
                ldsm_x4(al[mi], ra + ARR * 4);
            }
            #pragma unroll
            for (int ni = 0; ni < 4; ni++) {
                uint32_t rb = sbase + (2 * ARR + boff + ni * 8 * WS + kw) * 4;
                uint32_t bh[2], bl[2];
                ldsm_x2(bh, rb);
                ldsm_x2(bl, rb + ARR * 4);
                #pragma unroll
                for (int mi = 0; mi < 4; mi++) {
                    mma_f16(acc[mi][ni], ah[mi], bh);
                    mma_f16(acc[mi][ni], ah[mi], bl);
                    mma_f16(acc[mi][ni], al[mi], bh);
                }
            }
        }
    }

    #pragma unroll
    for (int mi = 0; mi < 4; mi++) {
        int r0 = m0 + mw * 64 + mi * 16 + g;
        #pragma unroll
        for (int ni = 0; ni < 4; ni++) {
            int c = n0 + nw * 32 + ni * 8 + 2 * t;
            *(float2*)&C[(size_t)r0 * N + c]       = make_float2(acc[mi][ni][0], acc[mi][ni][1]);
            *(float2*)&C[(size_t)(r0 + 8) * N + c] = make_float2(acc[mi][ni][2], acc[mi][ni][3]);
        }
    }
}

// ---------------------------------------------------------------------------
// Per-head L2 norm + fp16 conversion (hi, optional lo residual).
// ---------------------------------------------------------------------------
__global__ __launch_bounds__(768) void headnorm_cvt_kernel(
    const float* __restrict__ X, __half* __restrict__ Hi,
    __half* __restrict__ Lo)
{
    const int row = blockIdx.x;
    const int t = threadIdx.x;
    float v = X[(size_t)row * D + t];
    float s = v * v;
    #pragma unroll
    for (int o = 16; o; o >>= 1) s += __shfl_xor_sync(0xffffffffu, s, o);
    __shared__ float ws[24];
    if ((t & 31) == 0) ws[t >> 5] = s;
    __syncthreads();
    int head = t >> 6;
    float sum = ws[head * 2] + ws[head * 2 + 1];
    float scale = 1.0f / fmaxf(sqrtf(sum), 1e-12f);
    float nv = v * scale;
    __half hb = __float2half_rn(nv);
    Hi[(size_t)row * D + t] = hb;
    if (Lo) Lo[(size_t)row * D + t] = __float2half_rn(nv - __half2float(hb));
}

// ---------------------------------------------------------------------------
// Elementwise fp32 -> fp16 (V).
// ---------------------------------------------------------------------------
__global__ __launch_bounds__(256) void vconv_kernel(
    const float* __restrict__ V, __half* __restrict__ Vh)
{
    int i = blockIdx.x * 256 + threadIdx.x;
    float4 v = ((const float4*)V)[i];
    uint2 h;
    h.x = pack2h(v.x, v.y);
    h.y = pack2h(v.z, v.w);
    ((uint2*)Vh)[i] = h;
}

// ---------------------------------------------------------------------------
// Flash attention (numerics == R7): S=(Qh+Ql).Kh^T ; P = fp16(p*2^-14) ;
// O += P.V^T. 64-q tile, 8 warps (4x2). K/V tiles double-buffered via
// cp.async (prefetch tile n+1 during compute of tile n).
// smem (words): Qh[2304] Ql[2304] | stage0 Kh/Vh | stage1 Kh/Vh | Ph[2304]
// ---------------------------------------------------------------------------
#define VS 36
#define TW (64 * VS)            // 2304 words per tile array
#define PSCALE   6.103515625e-05f
#define PUNSCALE 16384.0f
__global__ __launch_bounds__(256) void attn_kernel(
    const __half* __restrict__ Qh16, const __half* __restrict__ Ql16,
    const __half* __restrict__ Kh16, const __half* __restrict__ Vh16,
    float* __restrict__ O, const void* __restrict__ invt_raw)
{
    extern __shared__ uint32_t sm[];
    const uint32_t sb = smem_u32(sm);
    const int QhW = 0, QlW = TW, KVW = 2 * TW, PhW = 6 * TW;
    float* part = (float*)(sm + 7 * TW);     // [8][16]

    const int tid = threadIdx.x;
    const int w = tid >> 5, lane = tid & 31;
    const int g = lane >> 2, t = lane & 3;
    const int mw = w >> 1, nw = w & 1;       // 4 x 2 warp grid
    const int h = blockIdx.y;
    const int q0 = blockIdx.x * 64;
    const float invt = decode_scalar(invt_raw);

    // ldmatrix lane offsets (words)
    const int aoff  = (mw * 16 + (lane & 15)) * VS + (lane >> 4) * 4;
    const int boff  = (nw * 32 + (lane & 7)) * VS + ((lane >> 3) & 1) * 4;
    const int voffr = (lane & 7) + ((lane >> 3) & 1) * 8;

    // Q tile fill (preconverted fp16, one-time)
    #pragma unroll
    for (int p = 0; p < 4; p++) {
        int idx = tid + p * 256;             // 1024: 64 rows x 16 uint2
        int r = idx >> 4, c4 = idx & 15;
        const size_t go = (size_t)(q0 + r) * D + h * HD + c4 * 4;
        *(uint2*)&sm[QhW + r * VS + c4 * 2] = *(const uint2*)(Qh16 + go);
        *(uint2*)&sm[QlW + r * VS + c4 * 2] = *(const uint2*)(Ql16 + go);
    }

    float l0 = 0.f, l1 = 0.f;
    float o[4][4];
    #pragma unroll
    for (int ni = 0; ni < 4; ni++)
        #pragma unroll
        for (int e = 0; e < 4; e++) o[ni][e] = 0.f;

    const int r0 = mw * 16 + g;

    // async prefetch of K/V tile -> stage st (512 x 16B chunks per array)
    auto issue_tile = [&](int n0, int st) {
        #pragma unroll
        for (int p = 0; p < 2; p++) {
            int idx = tid + p * 256;
            int r = idx >> 3, c8 = idx & 7;
            const size_t go = (size_t)(n0 + r) * D + h * HD + c8 * 8;
            uint32_t sk = sb + (KVW + st * 2 * TW + r * VS + c8 * 4) * 4;
            cp16(sk, Kh16 + go);
            cp16(sk + TW * 4, Vh16 + go);
        }
    };

    issue_tile(0, 0);
    asm volatile("cp.async.commit_group;" ::: "memory");

    for (int n0 = 0, it = 0; n0 < B2; n0 += 64, it++) {
        const int st = it & 1;
        if (n0 + 64 < B2) issue_tile(n0 + 64, st ^ 1);
        asm volatile("cp.async.commit_group;" ::: "memory");
        asm volatile("cp.async.wait_group 1;" ::: "memory");
        __syncthreads();                      // tile n visible to all

        const uint32_t KhB = sb + (KVW + st * 2 * TW) * 4;
        const uint32_t VhB = KhB + TW * 4;

        // S = (Qh + Ql) . Kh^T
        float s[4][4];
        #pragma unroll
        for (int ni = 0; ni < 4; ni++)
            #pragma unroll
            for (int e = 0; e < 4; e++) s[ni][e] = 0.f;

        #pragma unroll
        for (int ks = 0; ks < 4; ks++) {
            int kw = ks * 8;
            uint32_t ah[4], al[4];
            ldsm_x4(ah, sb + (QhW + aoff + kw) * 4);
            ldsm_x4(al, sb + (QlW + aoff + kw) * 4);
            #pragma unroll
            for (int ni = 0; ni < 4; ni++) {
                uint32_t bh[2];
                ldsm_x2(bh, KhB + (boff + ni * 8 * VS + kw) * 4);
                mma_f16(s[ni], ah, bh);
                mma_f16(s[ni], al, bh);
            }
        }

        // exp + fp32 row-sum partials + store scaled-fp16 P
        float rs0 = 0.f, rs1 = 0.f;
        #pragma unroll
        for (int ni = 0; ni < 4; ni++) {
            float p0 = __expf(s[ni][0] * invt);
            float p1 = __expf(s[ni][1] * invt);
            float p2 = __expf(s[ni][2] * invt);
            float p3 = __expf(s[ni][3] * invt);
            rs0 += p0 + p1; rs1 += p2 + p3;
            int wp = nw * 16 + ni * 4 + t;
            sm[PhW + r0 * VS + wp]       = pack2h(p0 * PSCALE, p1 * PSCALE);
            sm[PhW + (r0 + 8) * VS + wp] = pack2h(p2 * PSCALE, p3 * PSCALE);
        }
        rs0 += __shfl_xor_sync(0xffffffffu, rs0, 1);
        rs0 += __shfl_xor_sync(0xffffffffu, rs0, 2);
        rs1 += __shfl_xor_sync(0xffffffffu, rs1, 1);
        rs1 += __shfl_xor_sync(0xffffffffu, rs1, 2);
        if (t == 0) {
            part[w * 16 + g]     = rs0;
            part[w * 16 + g + 8] = rs1;
        }
        __syncthreads();

        // O += P . V  (V transposed inside ldmatrix)
        #pragma unroll
        for (int ks = 0; ks < 4; ks++) {
            int kw = ks * 8;
            uint32_t ap[4];
            ldsm_x4(ap, sb + (PhW + aoff + kw) * 4);
            #pragma unroll
            for (int ni = 0; ni < 4; ni++) {
                uint32_t bv[2];
                uint32_t rv = VhB + ((ks * 16 + voffr) * VS + nw * 16 + ni * 4) * 4;
                ldsm_x2t(bv, rv);
                mma_f16(o[ni], ap, bv);
            }
        }

        l0 += part[(2 * mw) * 16 + g]     + part[(2 * mw + 1) * 16 + g];
        l1 += part[(2 * mw) * 16 + g + 8] + part[(2 * mw + 1) * 16 + g + 8];
        __syncthreads();                      // Ph/part reuse; stage st free
    }

    float i0 = PUNSCALE / l0, i1 = PUNSCALE / l1;
    #pragma unroll
    for (int ni = 0; ni < 4; ni++) {
        int c = h * HD + nw * 32 + ni * 8 + 2 * t;
        int gr0 = q0 + r0;
        *(float2*)&O[(size_t)gr0 * D + c] =
            make_float2(o[ni][0] * i0, o[ni][1] * i0);
        *(float2*)&O[(size_t)(gr0 + 8) * D + c] =
            make_float2(o[ni][2] * i1, o[ni][3] * i1);
    }
}

// ---------------------------------------------------------------------------
// Full-row L2 norm of X[2048, 768], in place.
// ---------------------------------------------------------------------------
__global__ __launch_bounds__(256) void rownorm_kernel(float* __restrict__ X)
{
    const int row = blockIdx.x;
    const int t = threadIdx.x;
    float* xr = X + (size_t)row * D;
    float s = 0.f;
    for (int i = t; i < D; i += 256) { float v = xr[i]; s += v * v; }
    #pragma unroll
    for (int o = 16; o; o >>= 1) s += __shfl_xor_sync(0xffffffffu, s, o);
    __shared__ float red[8];
    if ((t & 31) == 0) red[t >> 5] = s;
    __syncthreads();
    float tot = 0.f;
    #pragma unroll
    for (int i = 0; i < 8; i++) tot += red[i];
    float scale = 1.0f / fmaxf(sqrtf(tot), 1e-12f);
    for (int i = t; i < D; i += 256) xr[i] *= scale;
}

// ---------------------------------------------------------------------------
extern "C" void kernel_launch(void* const* d_in, const int* in_sizes, int n_in,
                              void* d_out, int out_size)
{
    (void)in_sizes; (void)n_in; (void)out_size;
    const float* x1 = (const float*)d_in[0];
    const float* x2 = (const float*)d_in[1];
    const float* Wq = (const float*)d_in[2];
    const float* Wk = (const float*)d_in[3];
    const float* Wv = (const float*)d_in[4];
    const float* Wo = (const float*)d_in[5];
    const void*  invt = d_in[6];
    float* out = (float*)d_out;

    void *pQ, *pK, *pV, *pO, *pQh, *pQl, *pKh, *pVh;
    cudaGetSymbolAddress(&pQ, g_Q);
    cudaGetSymbolAddress(&pK, g_K);
    cudaGetSymbolAddress(&pV, g_V);
    cudaGetSymbolAddress(&pO, g_O);
    cudaGetSymbolAddress(&pQh, g_Qh16);
    cudaGetSymbolAddress(&pQl, g_Ql16);
    cudaGetSymbolAddress(&pKh, g_Kh16);
    cudaGetSymbolAddress(&pVh, g_Vh16);

    // Projections (fp16x3, double-buffered, ldmatrix)
    const int gsmem = 2 * STG * 4;   // 81920 B
    cudaFuncSetAttribute(gemm_f16x3_kernel,
                         cudaFuncAttributeMaxDynamicSharedMemorySize, gsmem);
    gemm_f16x3_kernel<<<dim3(D/128, B1/128), 256, gsmem>>>(x1, Wq, (float*)pQ, B1, D, D);
    gemm_f16x3_kernel<<<dim3(D/128, B2/128), 256, gsmem>>>(x2, Wk, (float*)pK, B2, D, D);
    gemm_f16x3_kernel<<<dim3(D/128, B2/128), 256, gsmem>>>(x2, Wv, (float*)pV, B2, D, D);

    // Per-head cosine normalization + fp16 conversion
    headnorm_cvt_kernel<<<B1, 768>>>((float*)pQ, (__half*)pQh, (__half*)pQl);
    headnorm_cvt_kernel<<<B2, 768>>>((float*)pK, (__half*)pKh, nullptr);
    vconv_kernel<<<(B2 * D / 4) / 256, 256>>>((float*)pV, (__half*)pVh);

    // Flash attention (64-q tiles, cp.async double-buffered K/V)
    const int smem_bytes = (7 * TW) * 4 + 8 * 16 * 4;   // 65024 B
    cudaFuncSetAttribute(attn_kernel,
                         cudaFuncAttributeMaxDynamicSharedMemorySize, smem_bytes);
    attn_kernel<<<dim3(B1/64, H), 256, smem_bytes>>>(
        (__half*)pQh, (__half*)pQl, (__half*)pKh, (__half*)pVh, (float*)pO, invt);

    // Output projection into d_out, then in-place row norm
    gemm_f16x3_kernel<<<dim3(D/128, B1/128), 256, gsmem>>>((float*)pO, Wo, out, B1, D, D);
    rownorm_kernel<<<B1, 256>>>(out);
}

// round 13
// speedup vs baseline: 1.1030x; 1.0111x over previous
#include <cuda_runtime.h>
#include <cuda_fp16.h>
#include <math.h>
#include <stdint.h>

#define D   768
#define H   12
#define HD  64
#define B1  2048
#define B2  8192

// Scratch (allocation-free rule: __device__ globals)
__device__ float g_Q[B1 * D];
__device__ float g_K[B2 * D];
__device__ float g_V[B2 * D];
__device__ __half g_Qh16[B1 * D];
__device__ __half g_Ql16[B1 * D];
__device__ __half g_Kh16[B2 * D];
__device__ __half g_Vh16[B2 * D];
__device__ __half g_Oh16[B1 * D];
__device__ __half g_Ol16[B1 * D];
__device__ __half g_x1h[B1 * D], g_x1l[B1 * D];
__device__ __half g_x2h[B2 * D], g_x2l[B2 * D];
__device__ __half g_Wqh[D * D], g_Wql[D * D];
__device__ __half g_Wkh[D * D], g_Wkl[D * D];
__device__ __half g_Wvh[D * D], g_Wvl[D * D];
__device__ __half g_Woh[D * D], g_Wol[D * D];

__device__ __forceinline__ float decode_scalar(const void* p) {
    int iv = *(const int*)p;
    if (iv >= -1000000 && iv <= 1000000) return (float)iv;
    return *(const float*)p;
}

// ---- fp16 split helpers ----------------------------------------------------
__device__ __forceinline__ void split2h(float x0, float x1,
                                        uint32_t& hi, uint32_t& lo) {
    __half2 h = __floats2half2_rn(x0, x1);
    float r0 = x0 - __low2float(h);
    float r1 = x1 - __high2float(h);
    __half2 l = __floats2half2_rn(r0, r1);
    hi = *reinterpret_cast<uint32_t*>(&h);
    lo = *reinterpret_cast<uint32_t*>(&l);
}

__device__ __forceinline__ uint32_t pack2h(float x0, float x1) {
    __half2 h = __floats2half2_rn(x0, x1);
    return *reinterpret_cast<uint32_t*>(&h);
}

__device__ __forceinline__ void split4h(float4 v, uint2& hi, uint2& lo) {
    split2h(v.x, v.y, hi.x, lo.x);
    split2h(v.z, v.w, hi.y, lo.y);
}

// ---- mma + ldmatrix + cp.async ---------------------------------------------
__device__ __forceinline__ void mma_f16(float c[4], const uint32_t a[4],
                                        const uint32_t b[2]) {
    asm volatile(
        "mma.sync.aligned.m16n8k16.row.col.f32.f16.f16.f32 "
        "{%0,%1,%2,%3}, {%4,%5,%6,%7}, {%8,%9}, {%0,%1,%2,%3};"
        : "+f"(c[0]), "+f"(c[1]), "+f"(c[2]), "+f"(c[3])
        : "r"(a[0]), "r"(a[1]), "r"(a[2]), "r"(a[3]), "r"(b[0]), "r"(b[1]));
}

__device__ __forceinline__ uint32_t smem_u32(const void* p) {
    uint32_t a;
    asm("{ .reg .u64 t; cvta.to.shared.u64 t, %1; cvt.u32.u64 %0, t; }"
        : "=r"(a) : "l"(p));
    return a;
}

__device__ __forceinline__ void ldsm_x4(uint32_t r[4], uint32_t addr) {
    asm volatile("ldmatrix.sync.aligned.m8n8.x4.shared.b16 {%0,%1,%2,%3}, [%4];"
                 : "=r"(r[0]), "=r"(r[1]), "=r"(r[2]), "=r"(r[3]) : "r"(addr));
}
__device__ __forceinline__ void ldsm_x2(uint32_t r[2], uint32_t addr) {
    asm volatile("ldmatrix.sync.aligned.m8n8.x2.shared.b16 {%0,%1}, [%2];"
                 : "=r"(r[0]), "=r"(r[1]) : "r"(addr));
}
__device__ __forceinline__ void ldsm_x2t(uint32_t r[2], uint32_t addr) {
    asm volatile("ldmatrix.sync.aligned.m8n8.x2.trans.shared.b16 {%0,%1}, [%2];"
                 : "=r"(r[0]), "=r"(r[1]) : "r"(addr));
}
__device__ __forceinline__ void cp16(uint32_t saddr, const void* gaddr) {
    asm volatile("cp.async.cg.shared.global [%0], [%1], 16;"
                 :: "r"(saddr), "l"(gaddr) : "memory");
}

// ---------------------------------------------------------------------------
// fp32 -> fp16 hi/lo split, vectorized (n % 1024 == 0).
// ---------------------------------------------------------------------------
__global__ __launch_bounds__(256) void fsplit_kernel(
    const float* __restrict__ X, __half* __restrict__ Hi, __half* __restrict__ Lo)
{
    int i = blockIdx.x * 256 + threadIdx.x;
    float4 v = ((const float4*)X)[i];
    uint2 hi, lo; split4h(v, hi, lo);
    ((uint2*)Hi)[i] = hi;
    ((uint2*)Lo)[i] = lo;
}

// ---------------------------------------------------------------------------
// C[M,N] = A[M,K] * B[N,K]^T via fp16x3 mma, preconverted fp16 hi/lo inputs,
// cp.async double-buffered stages. Block tile 128x128, 8 warps (2x4),
// warp tile 64x32, K chunk 32 elements. WS=20 word row pitch.
// ---------------------------------------------------------------------------
#define WS   20
#define ARR  (128 * WS)
#define STG  (4 * ARR)
__global__ __launch_bounds__(256) void gemm_f16x3_kernel(
    const __half* __restrict__ Ah16, const __half* __restrict__ Al16,
    const __half* __restrict__ Bh16, const __half* __restrict__ Bl16,
    float* __restrict__ C, int M, int N, int K)
{
    extern __shared__ uint32_t S[];
    const uint32_t sb = smem_u32(S);

    const int tid = threadIdx.x;
    const int w = tid >> 5, lane = tid & 31;
    const int g = lane >> 2, t = lane & 3;
    const int mw = w >> 2, nw = w & 3;
    const int m0 = blockIdx.y * 128, n0 = blockIdx.x * 128;

    float acc[4][4][4];
    #pragma unroll
    for (int mi = 0; mi < 4; mi++)
        #pragma unroll
        for (int ni = 0; ni < 4; ni++)
            #pragma unroll
            for (int e = 0; e < 4; e++) acc[mi][ni][e] = 0.f;

    const int aoff = (mw * 64 + (lane & 15)) * WS + (lane >> 4) * 4;
    const int boff = (nw * 32 + (lane & 7)) * WS + ((lane >> 3) & 1) * 4;

    const __half* gp[4] = {Ah16, Al16, Bh16, Bl16};

    // async fill of one K-chunk into stage st (2048 cp16 over 256 threads)
    auto issue = [&](int ch, int st) {
        #pragma unroll
        for (int p = 0; p < 8; p++) {
            int arr = p >> 1;
            int j = (p & 1) * 256 + tid;      // 0..511
            int r = j >> 2, c8 = j & 3;
            int row = (arr < 2 ? m0 : n0) + r;
            const __half* ga = gp[arr] + (size_t)row * K + ch * 32 + c8 * 8;
            uint32_t sa = sb + (st * STG + arr * ARR + r * WS + c8 * 4) * 4;
            cp16(sa, ga);
        }
    };

    const int NCH = K >> 5;
    issue(0, 0);
    asm volatile("cp.async.commit_group;" ::: "memory");

    for (int ch = 0; ch < NCH; ch++) {
        const int st = ch & 1;
        if (ch + 1 < NCH) issue(ch + 1, st ^ 1);
        asm volatile("cp.async.commit_group;" ::: "memory");
        asm volatile("cp.async.wait_group 1;" ::: "memory");
        __syncthreads();

        const uint32_t sbase = sb + st * (STG * 4);
        #pragma unroll
        for (int ks = 0; ks < 2; ks++) {
            int kw = ks * 8;
            uint32_t ah[4][4], al[4][4];
            #pragma unroll
            for (int mi = 0; mi < 4; mi++) {
                uint32_t ra = sbase + (aoff + mi * 16 * WS + kw) * 4;
                ldsm_x4(ah[mi], ra);
                ldsm_x4(al[mi], ra + ARR * 4);
            }
            #pragma unroll
            for (int ni = 0; ni < 4; ni++) {
                uint32_t rb = sbase + (2 * ARR + boff + ni * 8 * WS + kw) * 4;
                uint32_t bh[2], bl[2];
                ldsm_x2(bh, rb);
                ldsm_x2(bl, rb + ARR * 4);
                #pragma unroll
                for (int mi = 0; mi < 4; mi++) {
                    mma_f16(acc[mi][ni], ah[mi], bh);
                    mma_f16(acc[mi][ni], ah[mi], bl);
                    mma_f16(acc[mi][ni], al[mi], bh);
                }
            }
        }
        __syncthreads();   // stage st free for re-issue next iteration
    }

    #pragma unroll
    for (int mi = 0; mi < 4; mi++) {
        int r0 = m0 + mw * 64 + mi * 16 + g;
        #pragma unroll
        for (int ni = 0; ni < 4; ni++) {
            int c = n0 + nw * 32 + ni * 8 + 2 * t;
            *(float2*)&C[(size_t)r0 * N + c]       = make_float2(acc[mi][ni][0], acc[mi][ni][1]);
            *(float2*)&C[(size_t)(r0 + 8) * N + c] = make_float2(acc[mi][ni][2], acc[mi][ni][3]);
        }
    }
}

// ---------------------------------------------------------------------------
// Per-head L2 norm + fp16 conversion (hi, optional lo residual).
// ---------------------------------------------------------------------------
__global__ __launch_bounds__(768) void headnorm_cvt_kernel(
    const float* __restrict__ X, __half* __restrict__ Hi,
    __half* __restrict__ Lo)
{
    const int row = blockIdx.x;
    const int t = threadIdx.x;
    float v = X[(size_t)row * D + t];
    float s = v * v;
    #pragma unroll
    for (int o = 16; o; o >>= 1) s += __shfl_xor_sync(0xffffffffu, s, o);
    __shared__ float ws[24];
    if ((t & 31) == 0) ws[t >> 5] = s;
    __syncthreads();
    int head = t >> 6;
    float sum = ws[head * 2] + ws[head * 2 + 1];
    float scale = 1.0f / fmaxf(sqrtf(sum), 1e-12f);
    float nv = v * scale;
    __half hb = __float2half_rn(nv);
    Hi[(size_t)row * D + t] = hb;
    if (Lo) Lo[(size_t)row * D + t] = __float2half_rn(nv - __half2float(hb));
}

// ---------------------------------------------------------------------------
// Elementwise fp32 -> fp16 (V).
// ---------------------------------------------------------------------------
__global__ __launch_bounds__(256) void vconv_kernel(
    const float* __restrict__ V, __half* __restrict__ Vh)
{
    int i = blockIdx.x * 256 + threadIdx.x;
    float4 v = ((const float4*)V)[i];
    uint2 h;
    h.x = pack2h(v.x, v.y);
    h.y = pack2h(v.z, v.w);
    ((uint2*)Vh)[i] = h;
}

// ---------------------------------------------------------------------------
// Flash attention: S=(Qh+Ql).Kh^T ; P kept in REGISTERS (C-fragment of S
// reinterpreted as A-fragment of PV mma, scaled by 2^-14) ; each warp
// accumulates O and row sums over ITS 32 keys across all tiles; the two
// key-half warps combine once in the epilogue via smem. Writes O as fp16
// hi/lo for the output GEMM. 64-q tile, cp.async double-buffered K/V.
// smem (words): Qh[TW] Ql[TW] | stage0 Kh/Vh | stage1 Kh/Vh  (6*TW)
// Epilogue reuses the stage region for the O/l exchange.
// ---------------------------------------------------------------------------
#define VS 36
#define TW (64 * VS)
#define PSCALE   6.103515625e-05f
#define PUNSCALE 16384.0f
__global__ __launch_bounds__(256) void attn_kernel(
    const __half* __restrict__ Qh16, const __half* __restrict__ Ql16,
    const __half* __restrict__ Kh16, const __half* __restrict__ Vh16,
    __half* __restrict__ Oh16, __half* __restrict__ Ol16,
    const void* __restrict__ invt_raw)
{
    extern __shared__ uint32_t sm[];
    const uint32_t sb = smem_u32(sm);
    const int QhW = 0, QlW = TW, KVW = 2 * TW;

    const int tid = threadIdx.x;
    const int w = tid >> 5, lane = tid & 31;
    const int g = lane >> 2, t = lane & 3;
    const int mw = w >> 1, nw = w & 1;       // 4 x 2 warp grid
    const int h = blockIdx.y;
    const int q0 = blockIdx.x * 64;
    const float invt = decode_scalar(invt_raw);

    const int aoff  = (mw * 16 + (lane & 15)) * VS + (lane >> 4) * 4;
    const int boff  = (nw * 32 + (lane & 7)) * VS + ((lane >> 3) & 1) * 4;
    const int voffr = (lane & 7) + ((lane >> 3) & 1) * 8;

    // Q tile fill (one-time)
    #pragma unroll
    for (int p = 0; p < 4; p++) {
        int idx = tid + p * 256;
        int r = idx >> 4, c4 = idx & 15;
        const size_t go = (size_t)(q0 + r) * D + h * HD + c4 * 4;
        *(uint2*)&sm[QhW + r * VS + c4 * 2] = *(const uint2*)(Qh16 + go);
        *(uint2*)&sm[QlW + r * VS + c4 * 2] = *(const uint2*)(Ql16 + go);
    }

    float rs0 = 0.f, rs1 = 0.f;              // per-thread p partial sums
    float o[8][4];                            // rows (r0, r0+8) x dims ni*8+2t(+1)
    #pragma unroll
    for (int ni = 0; ni < 8; ni++)
        #pragma unroll
        for (int e = 0; e < 4; e++) o[ni][e] = 0.f;

    auto issue_tile = [&](int n0, int st) {
        #pragma unroll
        for (int p = 0; p < 2; p++) {
            int idx = tid + p * 256;
            int r = idx >> 3, c8 = idx & 7;
            const size_t go = (size_t)(n0 + r) * D + h * HD + c8 * 8;
            uint32_t sk = sb + (KVW + st * 2 * TW + r * VS + c8 * 4) * 4;
            cp16(sk, Kh16 + go);
            cp16(sk + TW * 4, Vh16 + go);
        }
    };

    issue_tile(0, 0);
    asm volatile("cp.async.commit_group;" ::: "memory");

    for (int n0 = 0, it = 0; n0 < B2; n0 += 64, it++) {
        const int st = it & 1;
        if (n0 + 64 < B2) issue_tile(n0 + 64, st ^ 1);
        asm volatile("cp.async.commit_group;" ::: "memory");
        asm volatile("cp.async.wait_group 1;" ::: "memory");
        __syncthreads();

        const uint32_t KhB = sb + (KVW + st * 2 * TW) * 4;
        const uint32_t VhB = KhB + TW * 4;

        // S = (Qh + Ql) . Kh^T   (warp's 32 keys: cols nw*32 + ni*8 + 2t..)
        float s[4][4];
        #pragma unroll
        for (int ni = 0; ni < 4; ni++)
            #pragma unroll
            for (int e = 0; e < 4; e++) s[ni][e] = 0.f;

        #pragma unroll
        for (int ks = 0; ks < 4; ks++) {
            int kw = ks * 8;
            uint32_t ah[4], al[4];
            ldsm_x4(ah, sb + (QhW + aoff + kw) * 4);
            ldsm_x4(al, sb + (QlW + aoff + kw) * 4);
            #pragma unroll
            for (int ni = 0; ni < 4; ni++) {
                uint32_t bh[2];
                ldsm_x2(bh, KhB + (boff + ni * 8 * VS + kw) * 4);
                mma_f16(s[ni], ah, bh);
                mma_f16(s[ni], al, bh);
            }
        }

        // exp + per-thread row-sum partials + pack P into A-fragments
        float e4[4][4];
        #pragma unroll
        for (int ni = 0; ni < 4; ni++) {
            e4[ni][0] = __expf(s[ni][0] * invt);
            e4[ni][1] = __expf(s[ni][1] * invt);
            e4[ni][2] = __expf(s[ni][2] * invt);
            e4[ni][3] = __expf(s[ni][3] * invt);
            rs0 += e4[ni][0] + e4[ni][1];
            rs1 += e4[ni][2] + e4[ni][3];
        }

        // O += P . V over this warp's 32 keys (kg = k16 group)
        #pragma unroll
        for (int kg = 0; kg < 2; kg++) {
            uint32_t ap[4];
            ap[0] = pack2h(e4[2*kg][0]   * PSCALE, e4[2*kg][1]   * PSCALE);
            ap[1] = pack2h(e4[2*kg][2]   * PSCALE, e4[2*kg][3]   * PSCALE);
            ap[2] = pack2h(e4[2*kg+1][0] * PSCALE, e4[2*kg+1][1] * PSCALE);
            ap[3] = pack2h(e4[2*kg+1][2] * PSCALE, e4[2*kg+1][3] * PSCALE);
            #pragma unroll
            for (int ni = 0; ni < 8; ni++) {
                uint32_t bv[2];
                uint32_t rv = VhB +
                    ((nw * 32 + kg * 16 + voffr) * VS + ni * 4) * 4;
                ldsm_x2t(bv, rv);
                mma_f16(o[ni], ap, bv);
            }
        }
        __syncthreads();     // all warps done with stage st before re-issue
    }

    // ---- epilogue: combine the two key-half warps, normalize, write fp16 ----
    rs0 += __shfl_xor_sync(0xffffffffu, rs0, 1);
    rs0 += __shfl_xor_sync(0xffffffffu, rs0, 2);
    rs1 += __shfl_xor_sync(0xffffffffu, rs1, 1);
    rs1 += __shfl_xor_sync(0xffffffffu, rs1, 2);

    float* ox = (float*)(sm + KVW);          // [64 rows][68] padded
    float* lx = ox + 64 * 68;                // [64]
    if (nw == 0) {
        #pragma unroll
        for (int ni = 0; ni < 8; ni++) {
            int d0 = ni * 8 + 2 * t;
            *(float2*)&ox[(mw * 16 + g) * 68 + d0]     = make_float2(o[ni][0], o[ni][1]);
            *(float2*)&ox[(mw * 16 + g + 8) * 68 + d0] = make_float2(o[ni][2], o[ni][3]);
        }
        if (t == 0) { lx[mw * 16 + g] = rs0; lx[mw * 16 + g + 8] = rs1; }
    }
    __syncthreads();
    if (nw == 1) {
        float i0 = PUNSCALE / (lx[mw * 16 + g] + rs0);
        float i1 = PUNSCALE / (lx[mw * 16 + g + 8] + rs1);
        int row0 = q0 + mw * 16 + g;
        #pragma unroll
        for (int ni = 0; ni < 8; ni++) {
            int d0 = ni * 8 + 2 * t;
            int c = h * HD + d0;
            float2 a = *(float2*)&ox[(mw * 16 + g) * 68 + d0];
            float v0 = (a.x + o[ni][0]) * i0;
            float v1 = (a.y + o[ni][1]) * i0;
            uint32_t hi, lo;
            split2h(v0, v1, hi, lo);
            *(uint32_t*)(Oh16 + (size_t)row0 * D + c) = hi;
            *(uint32_t*)(Ol16 + (size_t)row0 * D + c) = lo;
            float2 b = *(float2*)&ox[(mw * 16 + g + 8) * 68 + d0];
            float v2 = (b.x + o[ni][2]) * i1;
            float v3 = (b.y + o[ni][3]) * i1;
            split2h(v2, v3, hi, lo);
            *(uint32_t*)(Oh16 + (size_t)(row0 + 8) * D + c) = hi;
            *(uint32_t*)(Ol16 + (size_t)(row0 + 8) * D + c) = lo;
        }
    }
}

// ---------------------------------------------------------------------------
// Full-row L2 norm of X[2048, 768], in place.
// ---------------------------------------------------------------------------
__global__ __launch_bounds__(256) void rownorm_kernel(float* __restrict__ X)
{
    const int row = blockIdx.x;
    const int t = threadIdx.x;
    float* xr = X + (size_t)row * D;
    float s = 0.f;
    for (int i = t; i < D; i += 256) { float v = xr[i]; s += v * v; }
    #pragma unroll
    for (int o = 16; o; o >>= 1) s += __shfl_xor_sync(0xffffffffu, s, o);
    __shared__ float red[8];
    if ((t & 31) == 0) red[t >> 5] = s;
    __syncthreads();
    float tot = 0.f;
    #pragma unroll
    for (int i = 0; i < 8; i++) tot += red[i];
    float scale = 1.0f / fmaxf(sqrtf(tot), 1e-12f);
    for (int i = t; i < D; i += 256) xr[i] *= scale;
}

// ---------------------------------------------------------------------------
extern "C" void kernel_launch(void* const* d_in, const int* in_sizes, int n_in,
                              void* d_out, int out_size)
{
    (void)in_sizes; (void)n_in; (void)out_size;
    const float* x1 = (const float*)d_in[0];
    const float* x2 = (const float*)d_in[1];
    const float* Wq = (const float*)d_in[2];
    const float* Wk = (const float*)d_in[3];
    const float* Wv = (const float*)d_in[4];
    const float* Wo = (const float*)d_in[5];
    const void*  invt = d_in[6];
    float* out = (float*)d_out;

    void *pQ, *pK, *pV, *pQh, *pQl, *pKh, *pVh, *pOh, *pOl;
    void *px1h, *px1l, *px2h, *px2l;
    void *pWqh, *pWql, *pWkh, *pWkl, *pWvh, *pWvl, *pWoh, *pWol;
    cudaGetSymbolAddress(&pQ, g_Q);
    cudaGetSymbolAddress(&pK, g_K);
    cudaGetSymbolAddress(&pV, g_V);
    cudaGetSymbolAddress(&pQh, g_Qh16);
    cudaGetSymbolAddress(&pQl, g_Ql16);
    cudaGetSymbolAddress(&pKh, g_Kh16);
    cudaGetSymbolAddress(&pVh, g_Vh16);
    cudaGetSymbolAddress(&pOh, g_Oh16);
    cudaGetSymbolAddress(&pOl, g_Ol16);
    cudaGetSymbolAddress(&px1h, g_x1h);
    cudaGetSymbolAddress(&px1l, g_x1l);
    cudaGetSymbolAddress(&px2h, g_x2h);
    cudaGetSymbolAddress(&px2l, g_x2l);
    cudaGetSymbolAddress(&pWqh, g_Wqh);
    cudaGetSymbolAddress(&pWql, g_Wql);
    cudaGetSymbolAddress(&pWkh, g_Wkh);
    cudaGetSymbolAddress(&pWkl, g_Wkl);
    cudaGetSymbolAddress(&pWvh, g_Wvh);
    cudaGetSymbolAddress(&pWvl, g_Wvl);
    cudaGetSymbolAddress(&pWoh, g_Woh);
    cudaGetSymbolAddress(&pWol, g_Wol);

    // Preconvert GEMM operands to fp16 hi/lo
    fsplit_kernel<<<B1 * D / 1024, 256>>>(x1, (__half*)px1h, (__half*)px1l);
    fsplit_kernel<<<B2 * D / 1024, 256>>>(x2, (__half*)px2h, (__half*)px2l);
    fsplit_kernel<<<D * D / 1024, 256>>>(Wq, (__half*)pWqh, (__half*)pWql);
    fsplit_kernel<<<D * D / 1024, 256>>>(Wk, (__half*)pWkh, (__half*)pWkl);
    fsplit_kernel<<<D * D / 1024, 256>>>(Wv, (__half*)pWvh, (__half*)pWvl);
    fsplit_kernel<<<D * D / 1024, 256>>>(Wo, (__half*)pWoh, (__half*)pWol);

    // Projections (fp16x3, cp.async double-buffered)
    const int gsmem = 2 * STG * 4;   // 81920 B
    cudaFuncSetAttribute(gemm_f16x3_kernel,
                         cudaFuncAttributeMaxDynamicSharedMemorySize, gsmem);
    gemm_f16x3_kernel<<<dim3(D/128, B1/128), 256, gsmem>>>(
        (__half*)px1h, (__half*)px1l, (__half*)pWqh, (__half*)pWql,
        (float*)pQ, B1, D, D);
    gemm_f16x3_kernel<<<dim3(D/128, B2/128), 256, gsmem>>>(
        (__half*)px2h, (__half*)px2l, (__half*)pWkh, (__half*)pWkl,
        (float*)pK, B2, D, D);
    gemm_f16x3_kernel<<<dim3(D/128, B2/128), 256, gsmem>>>(
        (__half*)px2h, (__half*)px2l, (__half*)pWvh, (__half*)pWvl,
        (float*)pV, B2, D, D);

    // Per-head cosine normalization + fp16 conversion
    headnorm_cvt_kernel<<<B1, 768>>>((float*)pQ, (__half*)pQh, (__half*)pQl);
    headnorm_cvt_kernel<<<B2, 768>>>((float*)pK, (__half*)pKh, nullptr);
    vconv_kernel<<<(B2 * D / 4) / 256, 256>>>((float*)pV, (__half*)pVh);

    // Flash attention (register-P, deferred cross-warp combine)
    const int smem_bytes = 6 * TW * 4;   // 55296 B
    cudaFuncSetAttribute(attn_kernel,
                         cudaFuncAttributeMaxDynamicSharedMemorySize, smem_bytes);
    attn_kernel<<<dim3(B1/64, H), 256, smem_bytes>>>(
        (__half*)pQh, (__half*)pQl, (__half*)pKh, (__half*)pVh,
        (__half*)pOh, (__half*)pOl, invt);

    // Output projection into d_out, then in-place row norm
    gemm_f16x3_kernel<<<dim3(D/128, B1/128), 256, gsmem>>>(
        (__half*)pOh, (__half*)pOl, (__half*)pWoh, (__half*)pWol,
        out, B1, D, D);
    rownorm_kernel<<<B1, 256>>>(out);
}

// round 16
// speedup vs baseline: 1.2170x; 1.1033x over previous
#include <cuda_runtime.h>
#include <cuda_fp16.h>
#include <math.h>
#include <stdint.h>

#define D   768
#define H   12
#define HD  64
#define B1  2048
#define B2  8192

// Scratch (allocation-free rule: __device__ globals)
__device__ float g_Q[B1 * D];
__device__ float g_K[B2 * D];
__device__ __half g_Qh16[B1 * D];
__device__ __half g_Ql16[B1 * D];
__device__ __half g_Kh16[B2 * D];
__device__ __half g_Vh16[B2 * D];
__device__ __half g_Oh16[B1 * D];
__device__ __half g_Ol16[B1 * D];
__device__ __half g_x1h[B1 * D], g_x1l[B1 * D];
__device__ __half g_x2h[B2 * D], g_x2l[B2 * D];
__device__ __half g_Wqh[D * D], g_Wql[D * D];
__device__ __half g_Wkh[D * D], g_Wkl[D * D];
__device__ __half g_Wvh[D * D], g_Wvl[D * D];
__device__ __half g_Woh[D * D], g_Wol[D * D];

__device__ __forceinline__ float decode_scalar(const void* p) {
    int iv = *(const int*)p;
    if (iv >= -1000000 && iv <= 1000000) return (float)iv;
    return *(const float*)p;
}

// ---- fp16 split helpers ----------------------------------------------------
__device__ __forceinline__ void split2h(float x0, float x1,
                                        uint32_t& hi, uint32_t& lo) {
    __half2 h = __floats2half2_rn(x0, x1);
    float r0 = x0 - __low2float(h);
    float r1 = x1 - __high2float(h);
    __half2 l = __floats2half2_rn(r0, r1);
    hi = *reinterpret_cast<uint32_t*>(&h);
    lo = *reinterpret_cast<uint32_t*>(&l);
}

__device__ __forceinline__ uint32_t pack2h(float x0, float x1) {
    __half2 h = __floats2half2_rn(x0, x1);
    return *reinterpret_cast<uint32_t*>(&h);
}

__device__ __forceinline__ void split4h(float4 v, uint2& hi, uint2& lo) {
    split2h(v.x, v.y, hi.x, lo.x);
    split2h(v.z, v.w, hi.y, lo.y);
}

// ---- mma + ldmatrix + cp.async ---------------------------------------------
__device__ __forceinline__ void mma_f16(float c[4], const uint32_t a[4],
                                        const uint32_t b[2]) {
    asm volatile(
        "mma.sync.aligned.m16n8k16.row.col.f32.f16.f16.f32 "
        "{%0,%1,%2,%3}, {%4,%5,%6,%7}, {%8,%9}, {%0,%1,%2,%3};"
        : "+f"(c[0]), "+f"(c[1]), "+f"(c[2]), "+f"(c[3])
        : "r"(a[0]), "r"(a[1]), "r"(a[2]), "r"(a[3]), "r"(b[0]), "r"(b[1]));
}

__device__ __forceinline__ uint32_t smem_u32(const void* p) {
    uint32_t a;
    asm("{ .reg .u64 t; cvta.to.shared.u64 t, %1; cvt.u32.u64 %0, t; }"
        : "=r"(a) : "l"(p));
    return a;
}

__device__ __forceinline__ void ldsm_x4(uint32_t r[4], uint32_t addr) {
    asm volatile("ldmatrix.sync.aligned.m8n8.x4.shared.b16 {%0,%1,%2,%3}, [%4];"
                 : "=r"(r[0]), "=r"(r[1]), "=r"(r[2]), "=r"(r[3]) : "r"(addr));
}
__device__ __forceinline__ void ldsm_x2(uint32_t r[2], uint32_t addr) {
    asm volatile("ldmatrix.sync.aligned.m8n8.x2.shared.b16 {%0,%1}, [%2];"
                 : "=r"(r[0]), "=r"(r[1]) : "r"(addr));
}
__device__ __forceinline__ void ldsm_x2t(uint32_t r[2], uint32_t addr) {
    asm volatile("ldmatrix.sync.aligned.m8n8.x2.trans.shared.b16 {%0,%1}, [%2];"
                 : "=r"(r[0]), "=r"(r[1]) : "r"(addr));
}
__device__ __forceinline__ void cp16(uint32_t saddr, const void* gaddr) {
    asm volatile("cp.async.cg.shared.global [%0], [%1], 16;"
                 :: "r"(saddr), "l"(gaddr) : "memory");
}

// ---------------------------------------------------------------------------
// Fused fp32 -> fp16 hi/lo split of all six GEMM operands (one launch).
// Block 256 threads, 1 float4 per thread.
// ---------------------------------------------------------------------------
__global__ __launch_bounds__(256) void fsplit6_kernel(
    const float* __restrict__ x1, const float* __restrict__ x2,
    const float* __restrict__ Wq, const float* __restrict__ Wk,
    const float* __restrict__ Wv, const float* __restrict__ Wo,
    __half* x1h, __half* x1l, __half* x2h, __half* x2l,
    __half* Wqh, __half* Wql, __half* Wkh, __half* Wkl,
    __half* Wvh, __half* Wvl, __half* Woh, __half* Wol)
{
    const int N1 = B1 * D / 4, N2 = B2 * D / 4, NW = D * D / 4;
    int i = blockIdx.x * 256 + threadIdx.x;
    const float* src; __half *hi, *lo; int off;
    if (i < N1)                     { src = x1; hi = x1h; lo = x1l; off = i; }
    else if (i < N1 + N2)           { src = x2; hi = x2h; lo = x2l; off = i - N1; }
    else if (i < N1 + N2 + NW)      { src = Wq; hi = Wqh; lo = Wql; off = i - N1 - N2; }
    else if (i < N1 + N2 + 2 * NW)  { src = Wk; hi = Wkh; lo = Wkl; off = i - N1 - N2 - NW; }
    else if (i < N1 + N2 + 3 * NW)  { src = Wv; hi = Wvh; lo = Wvl; off = i - N1 - N2 - 2 * NW; }
    else                            { src = Wo; hi = Woh; lo = Wol; off = i - N1 - N2 - 3 * NW; }
    float4 v = ((const float4*)src)[off];
    uint2 h, l; split4h(v, h, l);
    ((uint2*)hi)[off] = h;
    ((uint2*)lo)[off] = l;
}

// ---------------------------------------------------------------------------
// C[M,N] = A[M,K]*B[N,K]^T via fp16 emulated mma.
// NPROD=3: ah*bh + ah*bl + al*bh (fp32-class). NPROD=2: ah*bh + al*bh
// (skips Bl entirely - loads and mma). OUTF16=1: write fp16 hi to Ch.
// Block tile 128x128, 8 warps (2x4), K chunk 32, cp.async double-buffered.
// ---------------------------------------------------------------------------
#define WS   20
#define ARR  (128 * WS)
template<int NPROD, int OUTF16>
__global__ __launch_bounds__(256) void gemm_kernel(
    const __half* __restrict__ Ah16, const __half* __restrict__ Al16,
    const __half* __restrict__ Bh16, const __half* __restrict__ Bl16,
    float* __restrict__ C, __half* __restrict__ Ch, int M, int N, int K)
{
    constexpr int NARR = (NPROD == 3) ? 4 : 3;
    constexpr int STGW = NARR * ARR;
    extern __shared__ uint32_t S[];
    const uint32_t sb = smem_u32(S);

    const int tid = threadIdx.x;
    const int w = tid >> 5, lane = tid & 31;
    const int g = lane >> 2, t = lane & 3;
    const int mw = w >> 2, nw = w & 3;
    const int m0 = blockIdx.y * 128, n0 = blockIdx.x * 128;

    float acc[4][4][4];
    #pragma unroll
    for (int mi = 0; mi < 4; mi++)
        #pragma unroll
        for (int ni = 0; ni < 4; ni++)
            #pragma unroll
            for (int e = 0; e < 4; e++) acc[mi][ni][e] = 0.f;

    const int aoff = (mw * 64 + (lane & 15)) * WS + (lane >> 4) * 4;
    const int boff = (nw * 32 + (lane & 7)) * WS + ((lane >> 3) & 1) * 4;

    const __half* gp[4] = {Ah16, Al16, Bh16, Bl16};

    auto issue = [&](int ch, int st) {
        #pragma unroll
        for (int p = 0; p < NARR * 2; p++) {
            int arr = p >> 1;
            int j = (p & 1) * 256 + tid;
            int r = j >> 2, c8 = j & 3;
            int row = (arr < 2 ? m0 : n0) + r;
            const __half* ga = gp[arr] + (size_t)row * K + ch * 32 + c8 * 8;
            cp16(sb + (st * STGW + arr * ARR + r * WS + c8 * 4) * 4, ga);
        }
    };

    const int NCH = K >> 5;
    issue(0, 0);
    asm volatile("cp.async.commit_group;" ::: "memory");

    for (int ch = 0; ch < NCH; ch++) {
        const int st = ch & 1;
        if (ch + 1 < NCH) issue(ch + 1, st ^ 1);
        asm volatile("cp.async.commit_group;" ::: "memory");
        asm volatile("cp.async.wait_group 1;" ::: "memory");
        __syncthreads();

        const uint32_t sbase = sb + st * (STGW * 4);
        #pragma unroll
        for (int ks = 0; ks < 2; ks++) {
            int kw = ks * 8;
            uint32_t ah[4][4], al[4][4];
            #pragma unroll
            for (int mi = 0; mi < 4; mi++) {
                uint32_t ra = sbase + (aoff + mi * 16 * WS + kw) * 4;
                ldsm_x4(ah[mi], ra);
                ldsm_x4(al[mi], ra + ARR * 4);
            }
            #pragma unroll
            for (int ni = 0; ni < 4; ni++) {
                uint32_t rb = sbase + (2 * ARR + boff + ni * 8 * WS + kw) * 4;
                uint32_t bh[2];
                ldsm_x2(bh, rb);
                if constexpr (NPROD == 3) {
                    uint32_t bl[2];
                    ldsm_x2(bl, rb + ARR * 4);
                    #pragma unroll
                    for (int mi = 0; mi < 4; mi++) {
                        mma_f16(acc[mi][ni], ah[mi], bh);
                        mma_f16(acc[mi][ni], ah[mi], bl);
                        mma_f16(acc[mi][ni], al[mi], bh);
                    }
                } else {
                    #pragma unroll
                    for (int mi = 0; mi < 4; mi++) {
                        mma_f16(acc[mi][ni], ah[mi], bh);
                        mma_f16(acc[mi][ni], al[mi], bh);
                    }
                }
            }
        }
        __syncthreads();
    }

    #pragma unroll
    for (int mi = 0; mi < 4; mi++) {
        int r0 = m0 + mw * 64 + mi * 16 + g;
        #pragma unroll
        for (int ni = 0; ni < 4; ni++) {
            int c = n0 + nw * 32 + ni * 8 + 2 * t;
            if constexpr (OUTF16) {
                *(uint32_t*)(Ch + (size_t)r0 * N + c) =
                    pack2h(acc[mi][ni][0], acc[mi][ni][1]);
                *(uint32_t*)(Ch + (size_t)(r0 + 8) * N + c) =
                    pack2h(acc[mi][ni][2], acc[mi][ni][3]);
            } else {
                *(float2*)&C[(size_t)r0 * N + c] =
                    make_float2(acc[mi][ni][0], acc[mi][ni][1]);
                *(float2*)&C[(size_t)(r0 + 8) * N + c] =
                    make_float2(acc[mi][ni][2], acc[mi][ni][3]);
            }
        }
    }
}

// ---------------------------------------------------------------------------
// Fused per-head L2 norm for Q (hi+lo out) and K (hi out), one launch.
// Blocks [0,B1) -> Q rows; [B1, B1+B2) -> K rows.
// ---------------------------------------------------------------------------
__global__ __launch_bounds__(768) void headnorm_qk_kernel(
    const float* __restrict__ Qf, const float* __restrict__ Kf,
    __half* __restrict__ Qh, __half* __restrict__ Ql, __half* __restrict__ Kh)
{
    int row = blockIdx.x;
    const float* X; __half *Hi, *Lo;
    if (row < B1) { X = Qf; Hi = Qh; Lo = Ql; }
    else          { row -= B1; X = Kf; Hi = Kh; Lo = nullptr; }

    const int t = threadIdx.x;
    float v = X[(size_t)row * D + t];
    float s = v * v;
    #pragma unroll
    for (int o = 16; o; o >>= 1) s += __shfl_xor_sync(0xffffffffu, s, o);
    __shared__ float ws[24];
    if ((t & 31) == 0) ws[t >> 5] = s;
    __syncthreads();
    int head = t >> 6;
    float sum = ws[head * 2] + ws[head * 2 + 1];
    float scale = 1.0f / fmaxf(sqrtf(sum), 1e-12f);
    float nv = v * scale;
    __half hb = __float2half_rn(nv);
    Hi[(size_t)row * D + t] = hb;
    if (Lo) Lo[(size_t)row * D + t] = __float2half_rn(nv - __half2float(hb));
}

// ---------------------------------------------------------------------------
// Flash attention (numerics == R13): S=(Qh+Ql).Kh^T ; register-P (*2^-14);
// per-warp O/rowsum accumulation over its 32 keys; one cross-warp combine
// in the epilogue. 3-stage cp.async K/V pipeline, ONE __syncthreads per tile.
// smem (words): Qh[TW] Ql[TW] | stage{0,1,2} Kh/Vh  = 8*TW (73728 B).
// ---------------------------------------------------------------------------
#define VS 36
#define TW (64 * VS)
#define PSCALE   6.103515625e-05f
#define PUNSCALE 16384.0f
__global__ __launch_bounds__(256) void attn_kernel(
    const __half* __restrict__ Qh16, const __half* __restrict__ Ql16,
    const __half* __restrict__ Kh16, const __half* __restrict__ Vh16,
    __half* __restrict__ Oh16, __half* __restrict__ Ol16,
    const void* __restrict__ invt_raw)
{
    extern __shared__ uint32_t sm[];
    const uint32_t sb = smem_u32(sm);
    const int QhW = 0, QlW = TW, KVW = 2 * TW;

    const int tid = threadIdx.x;
    const int w = tid >> 5, lane = tid & 31;
    const int g = lane >> 2, t = lane & 3;
    const int mw = w >> 1, nw = w & 1;       // 4 x 2 warp grid
    const int h = blockIdx.y;
    const int q0 = blockIdx.x * 64;
    const float invt = decode_scalar(invt_raw);

    const int aoff  = (mw * 16 + (lane & 15)) * VS + (lane >> 4) * 4;
    const int boff  = (nw * 32 + (lane & 7)) * VS + ((lane >> 3) & 1) * 4;
    const int voffr = (lane & 7) + ((lane >> 3) & 1) * 8;

    // Q tile fill (one-time)
    #pragma unroll
    for (int p = 0; p < 4; p++) {
        int idx = tid + p * 256;
        int r = idx >> 4, c4 = idx & 15;
        const size_t go = (size_t)(q0 + r) * D + h * HD + c4 * 4;
        *(uint2*)&sm[QhW + r * VS + c4 * 2] = *(const uint2*)(Qh16 + go);
        *(uint2*)&sm[QlW + r * VS + c4 * 2] = *(const uint2*)(Ql16 + go);
    }

    float rs0 = 0.f, rs1 = 0.f;
    float o[8][4];
    #pragma unroll
    for (int ni = 0; ni < 8; ni++)
        #pragma unroll
        for (int e = 0; e < 4; e++) o[ni][e] = 0.f;

    auto issue_tile = [&](int it, int st) {
        int n0 = it * 64;
        #pragma unroll
        for (int p = 0; p < 2; p++) {
            int idx = tid + p * 256;
            int r = idx >> 3, c8 = idx & 7;
            const size_t go = (size_t)(n0 + r) * D + h * HD + c8 * 8;
            uint32_t sk = sb + (KVW + st * 2 * TW + r * VS + c8 * 4) * 4;
            cp16(sk, Kh16 + go);
            cp16(sk + TW * 4, Vh16 + go);
        }
    };

    issue_tile(0, 0);
    asm volatile("cp.async.commit_group;" ::: "memory");
    issue_tile(1, 1);
    asm volatile("cp.async.commit_group;" ::: "memory");

    const int NT = B2 / 64;   // 128
    for (int it = 0; it < NT; it++) {
        const int st = it % 3;
        asm volatile("cp.async.wait_group 1;" ::: "memory");
        __syncthreads();                       // tile it visible everywhere
        if (it + 2 < NT) issue_tile(it + 2, (it + 2) % 3);
        asm volatile("cp.async.commit_group;" ::: "memory");

        const uint32_t KhB = sb + (KVW + st * 2 * TW) * 4;
        const uint32_t VhB = KhB + TW * 4;

        // S = (Qh + Ql) . Kh^T
        float s[4][4];
        #pragma unroll
        for (int ni = 0; ni < 4; ni++)
            #pragma unroll
            for (int e = 0; e < 4; e++) s[ni][e] = 0.f;

        #pragma unroll
        for (int ks = 0; ks < 4; ks++) {
            int kw = ks * 8;
            uint32_t ah[4], al[4];
            ldsm_x4(ah, sb + (QhW + aoff + kw) * 4);
            ldsm_x4(al, sb + (QlW + aoff + kw) * 4);
            #pragma unroll
            for (int ni = 0; ni < 4; ni++) {
                uint32_t bh[2];
                ldsm_x2(bh, KhB + (boff + ni * 8 * VS + kw) * 4);
                mma_f16(s[ni], ah, bh);
                mma_f16(s[ni], al, bh);
            }
        }

        // exp + per-thread row-sum partials
        float e4[4][4];
        #pragma unroll
        for (int ni = 0; ni < 4; ni++) {
            e4[ni][0] = __expf(s[ni][0] * invt);
            e4[ni][1] = __expf(s[ni][1] * invt);
            e4[ni][2] = __expf(s[ni][2] * invt);
            e4[ni][3] = __expf(s[ni][3] * invt);
            rs0 += e4[ni][0] + e4[ni][1];
            rs1 += e4[ni][2] + e4[ni][3];
        }

        // O += P . V over this warp's 32 keys
        #pragma unroll
        for (int kg = 0; kg < 2; kg++) {
            uint32_t ap[4];
            ap[0] = pack2h(e4[2*kg][0]   * PSCALE, e4[2*kg][1]   * PSCALE);
            ap[1] = pack2h(e4[2*kg][2]   * PSCALE, e4[2*kg][3]   * PSCALE);
            ap[2] = pack2h(e4[2*kg+1][0] * PSCALE, e4[2*kg+1][1] * PSCALE);
            ap[3] = pack2h(e4[2*kg+1][2] * PSCALE, e4[2*kg+1][3] * PSCALE);
            #pragma unroll
            for (int ni = 0; ni < 8; ni++) {
                uint32_t bv[2];
                uint32_t rv = VhB +
                    ((nw * 32 + kg * 16 + voffr) * VS + ni * 4) * 4;
                ldsm_x2t(bv, rv);
                mma_f16(o[ni], ap, bv);
            }
        }
        // no trailing sync: next iteration's top barrier bounds warp drift
    }

    __syncthreads();   // all compute done before stage region is reused

    // ---- epilogue: combine the two key-half warps, normalize, write fp16 ----
    rs0 += __shfl_xor_sync(0xffffffffu, rs0, 1);
    rs0 += __shfl_xor_sync(0xffffffffu, rs0, 2);
    rs1 += __shfl_xor_sync(0xffffffffu, rs1, 1);
    rs1 += __shfl_xor_sync(0xffffffffu, rs1, 2);

    float* ox = (float*)(sm + KVW);          // [64 rows][68] padded
    float* lx = ox + 64 * 68;                // [64]
    if (nw == 0) {
        #pragma unroll
        for (int ni = 0; ni < 8; ni++) {
            int d0 = ni * 8 + 2 * t;
            *(float2*)&ox[(mw * 16 + g) * 68 + d0]     = make_float2(o[ni][0], o[ni][1]);
            *(float2*)&ox[(mw * 16 + g + 8) * 68 + d0] = make_float2(o[ni][2], o[ni][3]);
        }
        if (t == 0) { lx[mw * 16 + g] = rs0; lx[mw * 16 + g + 8] = rs1; }
    }
    __syncthreads();
    if (nw == 1) {
        float i0 = PUNSCALE / (lx[mw * 16 + g] + rs0);
        float i1 = PUNSCALE / (lx[mw * 16 + g + 8] + rs1);
        int row0 = q0 + mw * 16 + g;
        #pragma unroll
        for (int ni = 0; ni < 8; ni++) {
            int d0 = ni * 8 + 2 * t;
            int c = h * HD + d0;
            float2 a = *(float2*)&ox[(mw * 16 + g) * 68 + d0];
            float v0 = (a.x + o[ni][0]) * i0;
            float v1 = (a.y + o[ni][1]) * i0;
            uint32_t hi, lo;
            split2h(v0, v1, hi, lo);
            *(uint32_t*)(Oh16 + (size_t)row0 * D + c) = hi;
            *(uint32_t*)(Ol16 + (size_t)row0 * D + c) = lo;
            float2 b = *(float2*)&ox[(mw * 16 + g + 8) * 68 + d0];
            float v2 = (b.x + o[ni][2]) * i1;
            float v3 = (b.y + o[ni][3]) * i1;
            split2h(v2, v3, hi, lo);
            *(uint32_t*)(Oh16 + (size_t)(row0 + 8) * D + c) = hi;
            *(uint32_t*)(Ol16 + (size_t)(row0 + 8) * D + c) = lo;
        }
    }
}

// ---------------------------------------------------------------------------
// Full-row L2 norm of X[2048, 768], in place.
// ---------------------------------------------------------------------------
__global__ __launch_bounds__(256) void rownorm_kernel(float* __restrict__ X)
{
    const int row = blockIdx.x;
    const int t = threadIdx.x;
    float* xr = X + (size_t)row * D;
    float s = 0.f;
    for (int i = t; i < D; i += 256) { float v = xr[i]; s += v * v; }
    #pragma unroll
    for (int o = 16; o; o >>= 1) s += __shfl_xor_sync(0xffffffffu, s, o);
    __shared__ float red[8];
    if ((t & 31) == 0) red[t >> 5] = s;
    __syncthreads();
    float tot = 0.f;
    #pragma unroll
    for (int i = 0; i < 8; i++) tot += red[i];
    float scale = 1.0f / fmaxf(sqrtf(tot), 1e-12f);
    for (int i = t; i < D; i += 256) xr[i] *= scale;
}

// ---------------------------------------------------------------------------
extern "C" void kernel_launch(void* const* d_in, const int* in_sizes, int n_in,
                              void* d_out, int out_size)
{
    (void)in_sizes; (void)n_in; (void)out_size;
    const float* x1 = (const float*)d_in[0];
    const float* x2 = (const float*)d_in[1];
    const float* Wq = (const float*)d_in[2];
    const float* Wk = (const float*)d_in[3];
    const float* Wv = (const float*)d_in[4];
    const float* Wo = (const float*)d_in[5];
    const void*  invt = d_in[6];
    float* out = (float*)d_out;

    void *pQ, *pK, *pQh, *pQl, *pKh, *pVh, *pOh, *pOl;
    void *px1h, *px1l, *px2h, *px2l;
    void *pWqh, *pWql, *pWkh, *pWkl, *pWvh, *pWvl, *pWoh, *pWol;
    cudaGetSymbolAddress(&pQ, g_Q);
    cudaGetSymbolAddress(&pK, g_K);
    cudaGetSymbolAddress(&pQh, g_Qh16);
    cudaGetSymbolAddress(&pQl, g_Ql16);
    cudaGetSymbolAddress(&pKh, g_Kh16);
    cudaGetSymbolAddress(&pVh, g_Vh16);
    cudaGetSymbolAddress(&pOh, g_Oh16);
    cudaGetSymbolAddress(&pOl, g_Ol16);
    cudaGetSymbolAddress(&px1h, g_x1h);
    cudaGetSymbolAddress(&px1l, g_x1l);
    cudaGetSymbolAddress(&px2h, g_x2h);
    cudaGetSymbolAddress(&px2l, g_x2l);
    cudaGetSymbolAddress(&pWqh, g_Wqh);
    cudaGetSymbolAddress(&pWql, g_Wql);
    cudaGetSymbolAddress(&pWkh, g_Wkh);
    cudaGetSymbolAddress(&pWkl, g_Wkl);
    cudaGetSymbolAddress(&pWvh, g_Wvh);
    cudaGetSymbolAddress(&pWvl, g_Wvl);
    cudaGetSymbolAddress(&pWoh, g_Woh);
    cudaGetSymbolAddress(&pWol, g_Wol);

    // [1] fused operand split
    const int NSPLIT = (B1 * D + B2 * D + 4 * D * D) / 1024;   // 9984 blocks
    fsplit6_kernel<<<NSPLIT, 256>>>(
        x1, x2, Wq, Wk, Wv, Wo,
        (__half*)px1h, (__half*)px1l, (__half*)px2h, (__half*)px2l,
        (__half*)pWqh, (__half*)pWql, (__half*)pWkh, (__half*)pWkl,
        (__half*)pWvh, (__half*)pWvl, (__half*)pWoh, (__half*)pWol);

    const int gs3 = 2 * 4 * ARR * 4;   // 81920 B (NPROD=3)
    const int gs2 = 2 * 3 * ARR * 4;   // 61440 B (NPROD=2)
    cudaFuncSetAttribute(gemm_kernel<3,0>,
                         cudaFuncAttributeMaxDynamicSharedMemorySize, gs3);
    cudaFuncSetAttribute(gemm_kernel<2,1>,
                         cudaFuncAttributeMaxDynamicSharedMemorySize, gs2);
    cudaFuncSetAttribute(gemm_kernel<2,0>,
                         cudaFuncAttributeMaxDynamicSharedMemorySize, gs2);

    // [2] Q projection (3-term, fp32 out)
    gemm_kernel<3,0><<<dim3(D/128, B1/128), 256, gs3>>>(
        (__half*)px1h, (__half*)px1l, (__half*)pWqh, (__half*)pWql,
        (float*)pQ, nullptr, B1, D, D);
    // [3] K projection (3-term, fp32 out)
    gemm_kernel<3,0><<<dim3(D/128, B2/128), 256, gs3>>>(
        (__half*)px2h, (__half*)px2l, (__half*)pWkh, (__half*)pWkl,
        (float*)pK, nullptr, B2, D, D);
    // [4] V projection (2-term, fp16 out direct)
    gemm_kernel<2,1><<<dim3(D/128, B2/128), 256, gs2>>>(
        (__half*)px2h, (__half*)px2l, (__half*)pWvh, (__half*)pWvl,
        nullptr, (__half*)pVh, B2, D, D);

    // [5] fused Q/K head-norm + fp16 conversion
    headnorm_qk_kernel<<<B1 + B2, 768>>>(
        (float*)pQ, (float*)pK, (__half*)pQh, (__half*)pQl, (__half*)pKh);

    // [6] flash attention (profiled by ncu -s 5 -c 1)
    const int smem_bytes = 8 * TW * 4;   // 73728 B
    cudaFuncSetAttribute(attn_kernel,
                         cudaFuncAttributeMaxDynamicSharedMemorySize, smem_bytes);
    attn_kernel<<<dim3(B1/64, H), 256, smem_bytes>>>(
        (__half*)pQh, (__half*)pQl, (__half*)pKh, (__half*)pVh,
        (__half*)pOh, (__half*)pOl, invt);

    // [7] output projection (2-term, fp32 into d_out)
    gemm_kernel<2,0><<<dim3(D/128, B1/128), 256, gs2>>>(
        (__half*)pOh, (__half*)pOl, (__half*)pWoh, (__half*)pWol,
        out, nullptr, B1, D, D);
    // [8] row norm
    rownorm_kernel<<<B1, 256>>>(out);
}

// round 17
// speedup vs baseline: 1.2744x; 1.0472x over previous
#include <cuda_runtime.h>
#include <cuda_fp16.h>
#include <math.h>
#include <stdint.h>

#define D   768
#define H   12
#define HD  64
#define B1  2048
#define B2  8192

// Scratch (allocation-free rule: __device__ globals)
__device__ float g_Q[B1 * D];
__device__ float g_K[B2 * D];
__device__ __half g_Qh16[B1 * D];
__device__ __half g_Ql16[B1 * D];
__device__ __half g_Kh16[B2 * D];
__device__ __half g_Vh16[B2 * D];
__device__ __half g_Oh16[B1 * D];
__device__ __half g_Ol16[B1 * D];
__device__ __half g_x1h[B1 * D], g_x1l[B1 * D];
__device__ __half g_x2h[B2 * D], g_x2l[B2 * D];
__device__ __half g_Wqh[D * D], g_Wql[D * D];
__device__ __half g_Wkh[D * D], g_Wkl[D * D];
__device__ __half g_Wvh[D * D], g_Wvl[D * D];
__device__ __half g_Woh[D * D], g_Wol[D * D];

__device__ __forceinline__ float decode_scalar(const void* p) {
    int iv = *(const int*)p;
    if (iv >= -1000000 && iv <= 1000000) return (float)iv;
    return *(const float*)p;
}

// ---- fp16 split helpers ----------------------------------------------------
__device__ __forceinline__ void split2h(float x0, float x1,
                                        uint32_t& hi, uint32_t& lo) {
    __half2 h = __floats2half2_rn(x0, x1);
    float r0 = x0 - __low2float(h);
    float r1 = x1 - __high2float(h);
    __half2 l = __floats2half2_rn(r0, r1);
    hi = *reinterpret_cast<uint32_t*>(&h);
    lo = *reinterpret_cast<uint32_t*>(&l);
}

__device__ __forceinline__ uint32_t pack2h(float x0, float x1) {
    __half2 h = __floats2half2_rn(x0, x1);
    return *reinterpret_cast<uint32_t*>(&h);
}

__device__ __forceinline__ void split4h(float4 v, uint2& hi, uint2& lo) {
    split2h(v.x, v.y, hi.x, lo.x);
    split2h(v.z, v.w, hi.y, lo.y);
}

// ---- mma + ldmatrix + cp.async ---------------------------------------------
__device__ __forceinline__ void mma_f16(float c[4], const uint32_t a[4],
                                        const uint32_t b[2]) {
    asm volatile(
        "mma.sync.aligned.m16n8k16.row.col.f32.f16.f16.f32 "
        "{%0,%1,%2,%3}, {%4,%5,%6,%7}, {%8,%9}, {%0,%1,%2,%3};"
        : "+f"(c[0]), "+f"(c[1]), "+f"(c[2]), "+f"(c[3])
        : "r"(a[0]), "r"(a[1]), "r"(a[2]), "r"(a[3]), "r"(b[0]), "r"(b[1]));
}

__device__ __forceinline__ uint32_t smem_u32(const void* p) {
    uint32_t a;
    asm("{ .reg .u64 t; cvta.to.shared.u64 t, %1; cvt.u32.u64 %0, t; }"
        : "=r"(a) : "l"(p));
    return a;
}

__device__ __forceinline__ void ldsm_x4(uint32_t r[4], uint32_t addr) {
    asm volatile("ldmatrix.sync.aligned.m8n8.x4.shared.b16 {%0,%1,%2,%3}, [%4];"
                 : "=r"(r[0]), "=r"(r[1]), "=r"(r[2]), "=r"(r[3]) : "r"(addr));
}
__device__ __forceinline__ void ldsm_x2(uint32_t r[2], uint32_t addr) {
    asm volatile("ldmatrix.sync.aligned.m8n8.x2.shared.b16 {%0,%1}, [%2];"
                 : "=r"(r[0]), "=r"(r[1]) : "r"(addr));
}
__device__ __forceinline__ void ldsm_x2t(uint32_t r[2], uint32_t addr) {
    asm volatile("ldmatrix.sync.aligned.m8n8.x2.trans.shared.b16 {%0,%1}, [%2];"
                 : "=r"(r[0]), "=r"(r[1]) : "r"(addr));
}
__device__ __forceinline__ void cp16(uint32_t saddr, const void* gaddr) {
    asm volatile("cp.async.cg.shared.global [%0], [%1], 16;"
                 :: "r"(saddr), "l"(gaddr) : "memory");
}

// ---------------------------------------------------------------------------
// Fused fp32 -> fp16 hi/lo split of all six GEMM operands (one launch).
// ---------------------------------------------------------------------------
__global__ __launch_bounds__(256) void fsplit6_kernel(
    const float* __restrict__ x1, const float* __restrict__ x2,
    const float* __restrict__ Wq, const float* __restrict__ Wk,
    const float* __restrict__ Wv, const float* __restrict__ Wo,
    __half* x1h, __half* x1l, __half* x2h, __half* x2l,
    __half* Wqh, __half* Wql, __half* Wkh, __half* Wkl,
    __half* Wvh, __half* Wvl, __half* Woh, __half* Wol)
{
    const int N1 = B1 * D / 4, N2 = B2 * D / 4, NW = D * D / 4;
    int i = blockIdx.x * 256 + threadIdx.x;
    const float* src; __half *hi, *lo; int off;
    if (i < N1)                     { src = x1; hi = x1h; lo = x1l; off = i; }
    else if (i < N1 + N2)           { src = x2; hi = x2h; lo = x2l; off = i - N1; }
    else if (i < N1 + N2 + NW)      { src = Wq; hi = Wqh; lo = Wql; off = i - N1 - N2; }
    else if (i < N1 + N2 + 2 * NW)  { src = Wk; hi = Wkh; lo = Wkl; off = i - N1 - N2 - NW; }
    else if (i < N1 + N2 + 3 * NW)  { src = Wv; hi = Wvh; lo = Wvl; off = i - N1 - N2 - 2 * NW; }
    else                            { src = Wo; hi = Woh; lo = Wol; off = i - N1 - N2 - 3 * NW; }
    float4 v = ((const float4*)src)[off];
    uint2 h, l; split4h(v, h, l);
    ((uint2*)hi)[off] = h;
    ((uint2*)lo)[off] = l;
}

// ---------------------------------------------------------------------------
// C[M,N] = A[M,K]*B[N,K]^T via fp16 emulated mma.
// NPROD=3: ah*bh + ah*bl + al*bh. NPROD=2: ah*bh + al*bh (no Bl array).
// Block tile 128x128, 8 warps (2x4), K chunk 32, cp.async double-buffered.
// __launch_bounds__(256, 2): cap 128 regs -> 2 CTAs/SM (was 134 regs, 1 CTA,
// occ 12.4%, issue 13% per ncu R16).
// ---------------------------------------------------------------------------
#define WS   20
#define ARR  (128 * WS)
template<int NPROD, int OUTF16>
__global__ __launch_bounds__(256, 2) void gemm_kernel(
    const __half* __restrict__ Ah16, const __half* __restrict__ Al16,
    const __half* __restrict__ Bh16, const __half* __restrict__ Bl16,
    float* __restrict__ C, __half* __restrict__ Ch, int M, int N, int K)
{
    constexpr int NARR = (NPROD == 3) ? 4 : 3;
    constexpr int STGW = NARR * ARR;
    extern __shared__ uint32_t S[];
    const uint32_t sb = smem_u32(S);

    const int tid = threadIdx.x;
    const int w = tid >> 5, lane = tid & 31;
    const int g = lane >> 2, t = lane & 3;
    const int mw = w >> 2, nw = w & 3;
    const int m0 = blockIdx.y * 128, n0 = blockIdx.x * 128;

    float acc[4][4][4];
    #pragma unroll
    for (int mi = 0; mi < 4; mi++)
        #pragma unroll
        for (int ni = 0; ni < 4; ni++)
            #pragma unroll
            for (int e = 0; e < 4; e++) acc[mi][ni][e] = 0.f;

    const int aoff = (mw * 64 + (lane & 15)) * WS + (lane >> 4) * 4;
    const int boff = (nw * 32 + (lane & 7)) * WS + ((lane >> 3) & 1) * 4;

    const __half* gp[4] = {Ah16, Al16, Bh16, Bl16};

    auto issue = [&](int ch, int st) {
        #pragma unroll
        for (int p = 0; p < NARR * 2; p++) {
            int arr = p >> 1;
            int j = (p & 1) * 256 + tid;
            int r = j >> 2, c8 = j & 3;
            int row = (arr < 2 ? m0 : n0) + r;
            const __half* ga = gp[arr] + (size_t)row * K + ch * 32 + c8 * 8;
            cp16(sb + (st * STGW + arr * ARR + r * WS + c8 * 4) * 4, ga);
        }
    };

    const int NCH = K >> 5;
    issue(0, 0);
    asm volatile("cp.async.commit_group;" ::: "memory");

    for (int ch = 0; ch < NCH; ch++) {
        const int st = ch & 1;
        if (ch + 1 < NCH) issue(ch + 1, st ^ 1);
        asm volatile("cp.async.commit_group;" ::: "memory");
        asm volatile("cp.async.wait_group 1;" ::: "memory");
        __syncthreads();

        const uint32_t sbase = sb + st * (STGW * 4);
        #pragma unroll
        for (int ks = 0; ks < 2; ks++) {
            int kw = ks * 8;
            uint32_t ah[4][4], al[4][4];
            #pragma unroll
            for (int mi = 0; mi < 4; mi++) {
                uint32_t ra = sbase + (aoff + mi * 16 * WS + kw) * 4;
                ldsm_x4(ah[mi], ra);
                ldsm_x4(al[mi], ra + ARR * 4);
            }
            #pragma unroll
            for (int ni = 0; ni < 4; ni++) {
                uint32_t rb = sbase + (2 * ARR + boff + ni * 8 * WS + kw) * 4;
                uint32_t bh[2];
                ldsm_x2(bh, rb);
                if constexpr (NPROD == 3) {
                    uint32_t bl[2];
                    ldsm_x2(bl, rb + ARR * 4);
                    #pragma unroll
                    for (int mi = 0; mi < 4; mi++) {
                        mma_f16(acc[mi][ni], ah[mi], bh);
                        mma_f16(acc[mi][ni], ah[mi], bl);
                        mma_f16(acc[mi][ni], al[mi], bh);
                    }
                } else {
                    #pragma unroll
                    for (int mi = 0; mi < 4; mi++) {
                        mma_f16(acc[mi][ni], ah[mi], bh);
                        mma_f16(acc[mi][ni], al[mi], bh);
                    }
                }
            }
        }
        __syncthreads();
    }

    #pragma unroll
    for (int mi = 0; mi < 4; mi++) {
        int r0 = m0 + mw * 64 + mi * 16 + g;
        #pragma unroll
        for (int ni = 0; ni < 4; ni++) {
            int c = n0 + nw * 32 + ni * 8 + 2 * t;
            if constexpr (OUTF16) {
                *(uint32_t*)(Ch + (size_t)r0 * N + c) =
                    pack2h(acc[mi][ni][0], acc[mi][ni][1]);
                *(uint32_t*)(Ch + (size_t)(r0 + 8) * N + c) =
                    pack2h(acc[mi][ni][2], acc[mi][ni][3]);
            } else {
                *(float2*)&C[(size_t)r0 * N + c] =
                    make_float2(acc[mi][ni][0], acc[mi][ni][1]);
                *(float2*)&C[(size_t)(r0 + 8) * N + c] =
                    make_float2(acc[mi][ni][2], acc[mi][ni][3]);
            }
        }
    }
}

// ---------------------------------------------------------------------------
// Fused per-head L2 norm for Q (hi+lo out) and K (hi out), one launch.
// ---------------------------------------------------------------------------
__global__ __launch_bounds__(768) void headnorm_qk_kernel(
    const float* __restrict__ Qf, const float* __restrict__ Kf,
    __half* __restrict__ Qh, __half* __restrict__ Ql, __half* __restrict__ Kh)
{
    int row = blockIdx.x;
    const float* X; __half *Hi, *Lo;
    if (row < B1) { X = Qf; Hi = Qh; Lo = Ql; }
    else          { row -= B1; X = Kf; Hi = Kh; Lo = nullptr; }

    const int t = threadIdx.x;
    float v = X[(size_t)row * D + t];
    float s = v * v;
    #pragma unroll
    for (int o = 16; o; o >>= 1) s += __shfl_xor_sync(0xffffffffu, s, o);
    __shared__ float ws[24];
    if ((t & 31) == 0) ws[t >> 5] = s;
    __syncthreads();
    int head = t >> 6;
    float sum = ws[head * 2] + ws[head * 2 + 1];
    float scale = 1.0f / fmaxf(sqrtf(sum), 1e-12f);
    float nv = v * scale;
    __half hb = __float2half_rn(nv);
    Hi[(size_t)row * D + t] = hb;
    if (Lo) Lo[(size_t)row * D + t] = __float2half_rn(nv - __half2float(hb));
}

// ---------------------------------------------------------------------------
// Flash attention (numerics == R13): S=(Qh+Ql).Kh^T ; register-P (*2^-14);
// per-warp O/rowsum over its 32 keys; one cross-warp combine in epilogue.
// 3-stage cp.async K/V pipeline, one __syncthreads per tile.
// ---------------------------------------------------------------------------
#define VS 36
#define TW (64 * VS)
#define PSCALE   6.103515625e-05f
#define PUNSCALE 16384.0f
__global__ __launch_bounds__(256, 2) void attn_kernel(
    const __half* __restrict__ Qh16, const __half* __restrict__ Ql16,
    const __half* __restrict__ Kh16, const __half* __restrict__ Vh16,
    __half* __restrict__ Oh16, __half* __restrict__ Ol16,
    const void* __restrict__ invt_raw)
{
    extern __shared__ uint32_t sm[];
    const uint32_t sb = smem_u32(sm);
    const int QhW = 0, QlW = TW, KVW = 2 * TW;

    const int tid = threadIdx.x;
    const int w = tid >> 5, lane = tid & 31;
    const int g = lane >> 2, t = lane & 3;
    const int mw = w >> 1, nw = w & 1;       // 4 x 2 warp grid
    const int h = blockIdx.y;
    const int q0 = blockIdx.x * 64;
    const float invt = decode_scalar(invt_raw);

    const int aoff  = (mw * 16 + (lane & 15)) * VS + (lane >> 4) * 4;
    const int boff  = (nw * 32 + (lane & 7)) * VS + ((lane >> 3) & 1) * 4;
    const int voffr = (lane & 7) + ((lane >> 3) & 1) * 8;

    // Q tile fill (one-time)
    #pragma unroll
    for (int p = 0; p < 4; p++) {
        int idx = tid + p * 256;
        int r = idx >> 4, c4 = idx & 15;
        const size_t go = (size_t)(q0 + r) * D + h * HD + c4 * 4;
        *(uint2*)&sm[QhW + r * VS + c4 * 2] = *(const uint2*)(Qh16 + go);
        *(uint2*)&sm[QlW + r * VS + c4 * 2] = *(const uint2*)(Ql16 + go);
    }

    float rs0 = 0.f, rs1 = 0.f;
    float o[8][4];
    #pragma unroll
    for (int ni = 0; ni < 8; ni++)
        #pragma unroll
        for (int e = 0; e < 4; e++) o[ni][e] = 0.f;

    auto issue_tile = [&](int it, int st) {
        int n0 = it * 64;
        #pragma unroll
        for (int p = 0; p < 2; p++) {
            int idx = tid + p * 256;
            int r = idx >> 3, c8 = idx & 7;
            const size_t go = (size_t)(n0 + r) * D + h * HD + c8 * 8;
            uint32_t sk = sb + (KVW + st * 2 * TW + r * VS + c8 * 4) * 4;
            cp16(sk, Kh16 + go);
            cp16(sk + TW * 4, Vh16 + go);
        }
    };

    issue_tile(0, 0);
    asm volatile("cp.async.commit_group;" ::: "memory");
    issue_tile(1, 1);
    asm volatile("cp.async.commit_group;" ::: "memory");

    const int NT = B2 / 64;   // 128
    for (int it = 0; it < NT; it++) {
        const int st = it % 3;
        asm volatile("cp.async.wait_group 1;" ::: "memory");
        __syncthreads();
        if (it + 2 < NT) issue_tile(it + 2, (it + 2) % 3);
        asm volatile("cp.async.commit_group;" ::: "memory");

        const uint32_t KhB = sb + (KVW + st * 2 * TW) * 4;
        const uint32_t VhB = KhB + TW * 4;

        // S = (Qh + Ql) . Kh^T
        float s[4][4];
        #pragma unroll
        for (int ni = 0; ni < 4; ni++)
            #pragma unroll
            for (int e = 0; e < 4; e++) s[ni][e] = 0.f;

        #pragma unroll
        for (int ks = 0; ks < 4; ks++) {
            int kw = ks * 8;
            uint32_t ah[4], al[4];
            ldsm_x4(ah, sb + (QhW + aoff + kw) * 4);
            ldsm_x4(al, sb + (QlW + aoff + kw) * 4);
            #pragma unroll
            for (int ni = 0; ni < 4; ni++) {
                uint32_t bh[2];
                ldsm_x2(bh, KhB + (boff + ni * 8 * VS + kw) * 4);
                mma_f16(s[ni], ah, bh);
                mma_f16(s[ni], al, bh);
            }
        }

        // exp + per-thread row-sum partials
        float e4[4][4];
        #pragma unroll
        for (int ni = 0; ni < 4; ni++) {
            e4[ni][0] = __expf(s[ni][0] * invt);
            e4[ni][1] = __expf(s[ni][1] * invt);
            e4[ni][2] = __expf(s[ni][2] * invt);
            e4[ni][3] = __expf(s[ni][3] * invt);
            rs0 += e4[ni][0] + e4[ni][1];
            rs1 += e4[ni][2] + e4[ni][3];
        }

        // O += P . V over this warp's 32 keys
        #pragma unroll
        for (int kg = 0; kg < 2; kg++) {
            uint32_t ap[4];
            ap[0] = pack2h(e4[2*kg][0]   * PSCALE, e4[2*kg][1]   * PSCALE);
            ap[1] = pack2h(e4[2*kg][2]   * PSCALE, e4[2*kg][3]   * PSCALE);
            ap[2] = pack2h(e4[2*kg+1][0] * PSCALE, e4[2*kg+1][1] * PSCALE);
            ap[3] = pack2h(e4[2*kg+1][2] * PSCALE, e4[2*kg+1][3] * PSCALE);
            #pragma unroll
            for (int ni = 0; ni < 8; ni++) {
                uint32_t bv[2];
                uint32_t rv = VhB +
                    ((nw * 32 + kg * 16 + voffr) * VS + ni * 4) * 4;
                ldsm_x2t(bv, rv);
                mma_f16(o[ni], ap, bv);
            }
        }
    }

    __syncthreads();   // all compute done before stage region is reused

    // ---- epilogue: combine key-half warps, normalize, write fp16 ----
    rs0 += __shfl_xor_sync(0xffffffffu, rs0, 1);
    rs0 += __shfl_xor_sync(0xffffffffu, rs0, 2);
    rs1 += __shfl_xor_sync(0xffffffffu, rs1, 1);
    rs1 += __shfl_xor_sync(0xffffffffu, rs1, 2);

    float* ox = (float*)(sm + KVW);          // [64 rows][68] padded
    float* lx = ox + 64 * 68;                // [64]
    if (nw == 0) {
        #pragma unroll
        for (int ni = 0; ni < 8; ni++) {
            int d0 = ni * 8 + 2 * t;
            *(float2*)&ox[(mw * 16 + g) * 68 + d0]     = make_float2(o[ni][0], o[ni][1]);
            *(float2*)&ox[(mw * 16 + g + 8) * 68 + d0] = make_float2(o[ni][2], o[ni][3]);
        }
        if (t == 0) { lx[mw * 16 + g] = rs0; lx[mw * 16 + g + 8] = rs1; }
    }
    __syncthreads();
    if (nw == 1) {
        float i0 = PUNSCALE / (lx[mw * 16 + g] + rs0);
        float i1 = PUNSCALE / (lx[mw * 16 + g + 8] + rs1);
        int row0 = q0 + mw * 16 + g;
        #pragma unroll
        for (int ni = 0; ni < 8; ni++) {
            int d0 = ni * 8 + 2 * t;
            int c = h * HD + d0;
            float2 a = *(float2*)&ox[(mw * 16 + g) * 68 + d0];
            float v0 = (a.x + o[ni][0]) * i0;
            float v1 = (a.y + o[ni][1]) * i0;
            uint32_t hi, lo;
            split2h(v0, v1, hi, lo);
            *(uint32_t*)(Oh16 + (size_t)row0 * D + c) = hi;
            *(uint32_t*)(Ol16 + (size_t)row0 * D + c) = lo;
            float2 b = *(float2*)&ox[(mw * 16 + g + 8) * 68 + d0];
            float v2 = (b.x + o[ni][2]) * i1;
            float v3 = (b.y + o[ni][3]) * i1;
            split2h(v2, v3, hi, lo);
            *(uint32_t*)(Oh16 + (size_t)(row0 + 8) * D + c) = hi;
            *(uint32_t*)(Ol16 + (size_t)(row0 + 8) * D + c) = lo;
        }
    }
}

// ---------------------------------------------------------------------------
// Full-row L2 norm of X[2048, 768], in place.
// ---------------------------------------------------------------------------
__global__ __launch_bounds__(256) void rownorm_kernel(float* __restrict__ X)
{
    const int row = blockIdx.x;
    const int t = threadIdx.x;
    float* xr = X + (size_t)row * D;
    float s = 0.f;
    for (int i = t; i < D; i += 256) { float v = xr[i]; s += v * v; }
    #pragma unroll
    for (int o = 16; o; o >>= 1) s += __shfl_xor_sync(0xffffffffu, s, o);
    __shared__ float red[8];
    if ((t & 31) == 0) red[t >> 5] = s;
    __syncthreads();
    float tot = 0.f;
    #pragma unroll
    for (int i = 0; i < 8; i++) tot += red[i];
    float scale = 1.0f / fmaxf(sqrtf(tot), 1e-12f);
    for (int i = t; i < D; i += 256) xr[i] *= scale;
}

// ---------------------------------------------------------------------------
extern "C" void kernel_launch(void* const* d_in, const int* in_sizes, int n_in,
                              void* d_out, int out_size)
{
    (void)in_sizes; (void)n_in; (void)out_size;
    const float* x1 = (const float*)d_in[0];
    const float* x2 = (const float*)d_in[1];
    const float* Wq = (const float*)d_in[2];
    const float* Wk = (const float*)d_in[3];
    const float* Wv = (const float*)d_in[4];
    const float* Wo = (const float*)d_in[5];
    const void*  invt = d_in[6];
    float* out = (float*)d_out;

    void *pQ, *pK, *pQh, *pQl, *pKh, *pVh, *pOh, *pOl;
    void *px1h, *px1l, *px2h, *px2l;
    void *pWqh, *pWql, *pWkh, *pWkl, *pWvh, *pWvl, *pWoh, *pWol;
    cudaGetSymbolAddress(&pQ, g_Q);
    cudaGetSymbolAddress(&pK, g_K);
    cudaGetSymbolAddress(&pQh, g_Qh16);
    cudaGetSymbolAddress(&pQl, g_Ql16);
    cudaGetSymbolAddress(&pKh, g_Kh16);
    cudaGetSymbolAddress(&pVh, g_Vh16);
    cudaGetSymbolAddress(&pOh, g_Oh16);
    cudaGetSymbolAddress(&pOl, g_Ol16);
    cudaGetSymbolAddress(&px1h, g_x1h);
    cudaGetSymbolAddress(&px1l, g_x1l);
    cudaGetSymbolAddress(&px2h, g_x2h);
    cudaGetSymbolAddress(&px2l, g_x2l);
    cudaGetSymbolAddress(&pWqh, g_Wqh);
    cudaGetSymbolAddress(&pWql, g_Wql);
    cudaGetSymbolAddress(&pWkh, g_Wkh);
    cudaGetSymbolAddress(&pWkl, g_Wkl);
    cudaGetSymbolAddress(&pWvh, g_Wvh);
    cudaGetSymbolAddress(&pWvl, g_Wvl);
    cudaGetSymbolAddress(&pWoh, g_Woh);
    cudaGetSymbolAddress(&pWol, g_Wol);

    // [1] fused operand split
    const int NSPLIT = (B1 * D + B2 * D + 4 * D * D) / 1024;
    fsplit6_kernel<<<NSPLIT, 256>>>(
        x1, x2, Wq, Wk, Wv, Wo,
        (__half*)px1h, (__half*)px1l, (__half*)px2h, (__half*)px2l,
        (__half*)pWqh, (__half*)pWql, (__half*)pWkh, (__half*)pWkl,
        (__half*)pWvh, (__half*)pWvl, (__half*)pWoh, (__half*)pWol);

    const int gs3 = 2 * 4 * ARR * 4;   // 81920 B (NPROD=3)
    const int gs2 = 2 * 3 * ARR * 4;   // 61440 B (NPROD=2)
    cudaFuncSetAttribute(gemm_kernel<3,0>,
                         cudaFuncAttributeMaxDynamicSharedMemorySize, gs3);
    cudaFuncSetAttribute(gemm_kernel<2,1>,
                         cudaFuncAttributeMaxDynamicSharedMemorySize, gs2);
    cudaFuncSetAttribute(gemm_kernel<2,0>,
                         cudaFuncAttributeMaxDynamicSharedMemorySize, gs2);

    // [2] Q projection (3-term)
    gemm_kernel<3,0><<<dim3(D/128, B1/128), 256, gs3>>>(
        (__half*)px1h, (__half*)px1l, (__half*)pWqh, (__half*)pWql,
        (float*)pQ, nullptr, B1, D, D);
    // [3] K projection (3-term)
    gemm_kernel<3,0><<<dim3(D/128, B2/128), 256, gs3>>>(
        (__half*)px2h, (__half*)px2l, (__half*)pWkh, (__half*)pWkl,
        (float*)pK, nullptr, B2, D, D);
    // [4] V projection (2-term, fp16 out)
    gemm_kernel<2,1><<<dim3(D/128, B2/128), 256, gs2>>>(
        (__half*)px2h, (__half*)px2l, (__half*)pWvh, (__half*)pWvl,
        nullptr, (__half*)pVh, B2, D, D);

    // [5] fused Q/K head-norm + fp16 conversion
    headnorm_qk_kernel<<<B1 + B2, 768>>>(
        (float*)pQ, (float*)pK, (__half*)pQh, (__half*)pQl, (__half*)pKh);

    // [6] flash attention
    const int smem_bytes = 8 * TW * 4;   // 73728 B
    cudaFuncSetAttribute(attn_kernel,
                         cudaFuncAttributeMaxDynamicSharedMemorySize, smem_bytes);
    attn_kernel<<<dim3(B1/64, H), 256, smem_bytes>>>(
        (__half*)pQh, (__half*)pQl, (__half*)pKh, (__half*)pVh,
        (__half*)pOh, (__half*)pOl, invt);

    // [7] output projection (2-term, into d_out)
    gemm_kernel<2,0><<<dim3(D/128, B1/128), 256, gs2>>>(
        (__half*)pOh, (__half*)pOl, (__half*)pWoh, (__half*)pWol,
        out, nullptr, B1, D, D);
    // [8] row norm
    rownorm_kernel<<<B1, 256>>>(out);
}